// round 10
// baseline (speedup 1.0000x reference)
#include <cuda_runtime.h>
#include <cuda_fp16.h>
#include <cstdint>

#define BATCH 2
#define SEQ   2048
#define EMB   1024
#define HEADS 16
#define HDIM  64
#define BH    (BATCH*HEADS)
#define ROWS  (BATCH*SEQ)

// ---------------- scratch ----------------------------------------------------
__device__ __half g_xq[ROWS * EMB];
__device__ __half g_xk[ROWS * EMB];
__device__ __half g_xv[ROWS * EMB];
__device__ __half g_wq[EMB * EMB];
__device__ __half g_wk[EMB * EMB];
__device__ __half g_wv[EMB * EMB];
__device__ __half g_wo[EMB * EMB];
__device__ __half g_q[BH * SEQ * HDIM];    // [bh][s][d], pre-scaled 1/8
__device__ __half g_k[BH * SEQ * HDIM];    // [bh][s][d]
__device__ __half g_v[BH * HDIM * SEQ];    // [bh][d][s]
__device__ __half g_attn[ROWS * EMB];      // [b*S+s][h*64+d]
__device__ float  g_badj[BATCH * SEQ * SEQ];  // mask-fused adj, tile-permuted

// ---------------- helpers ---------------------------------------------------
__device__ __forceinline__ uint32_t pack_h2(float lo, float hi) {
    uint32_t r;
    asm("cvt.rn.f16x2.f32 %0, %1, %2;" : "=r"(r) : "f"(hi), "f"(lo));
    return r;
}
__device__ __forceinline__ void mmaH(float* d, const uint32_t* a, uint32_t b0, uint32_t b1) {
    asm volatile(
        "mma.sync.aligned.m16n8k16.row.col.f32.f16.f16.f32 "
        "{%0,%1,%2,%3}, {%4,%5,%6,%7}, {%8,%9}, {%0,%1,%2,%3};"
        : "+f"(d[0]), "+f"(d[1]), "+f"(d[2]), "+f"(d[3])
        : "r"(a[0]), "r"(a[1]), "r"(a[2]), "r"(a[3]), "r"(b0), "r"(b1));
}
__device__ __forceinline__ void ldsm4(uint32_t* r, uint32_t addr) {
    asm volatile("ldmatrix.sync.aligned.m8n8.x4.shared.b16 {%0,%1,%2,%3}, [%4];"
                 : "=r"(r[0]), "=r"(r[1]), "=r"(r[2]), "=r"(r[3]) : "r"(addr));
}
__device__ __forceinline__ void cpa16(uint32_t dst, const void* src) {
    asm volatile("cp.async.cg.shared.global [%0], [%1], 16;" :: "r"(dst), "l"(src));
}
__device__ __forceinline__ void cp_commit() { asm volatile("cp.async.commit_group;"); }
template<int N> __device__ __forceinline__ void cp_wait() {
    asm volatile("cp.async.wait_group %0;" :: "n"(N));
}

// ---------------- pre-pass ---------------------------------------------------
struct CvtBatch { const float4* s[7]; __half2* d[7]; int n4[7]; };
__global__ void cvt_batch_k(CvtBatch a) {
    const float4* s = a.s[blockIdx.y];
    __half2* d = a.d[blockIdx.y];
    int n = a.n4[blockIdx.y];
    for (int i = blockIdx.x * 256 + threadIdx.x; i < n; i += gridDim.x * 256) {
        float4 v = s[i];
        d[2 * i]     = __floats2half2_rn(v.x, v.y);
        d[2 * i + 1] = __floats2half2_rn(v.z, v.w);
    }
}

// badj[b][q][tile-permuted k]: p = j*16 + nt*2 + c  <->  k_in_tile = nt*8 + 2j + c
__global__ void make_badj_k(const float* __restrict__ adj, const int* __restrict__ mask,
                            float* __restrict__ out) {
    int idx = blockIdx.x * 256 + threadIdx.x;
    int p  = idx & 63;
    int base = idx >> 6;
    int kt = base & 31;
    int q  = (base >> 5) & 2047;
    int b  = base >> 16;
    int jj = p >> 4, nt = (p & 15) >> 1, c = p & 1;
    int k = kt * 64 + nt * 8 + 2 * jj + c;
    float v = adj[(size_t)q * SEQ + k];
    int m = mask[((size_t)b * SEQ + q) * SEQ + k];
    out[idx] = m ? v : -1e30f;
}

// ---------------- fp16 GEMM (unchanged) --------------------------------------
#define GEMM_SMEM 65536

struct GemmBatch {
    const __half* X[3]; const __half* W[3]; const float* bias[3];
    void* Y[3]; int layout[3]; float scale[3];
};

__global__ __launch_bounds__(256, 2) void gemm_h(GemmBatch args)
{
    extern __shared__ __align__(1024) char smem[];
    const uint32_t sb = (uint32_t)__cvta_generic_to_shared(smem);
    const int z = blockIdx.z;
    const __half* __restrict__ X = args.X[z];
    const __half* __restrict__ W = args.W[z];
    const float* __restrict__ bias = args.bias[z];
    void* Y = args.Y[z];
    const int layout = args.layout[z];
    const float scale = args.scale[z];

    const int tid = threadIdx.x, lane = tid & 31, wid = tid >> 5;
    const int g = lane >> 2, j = lane & 3;
    const int wm = (wid & 1) * 64, wn = (wid >> 1) * 32;
    const int m0 = blockIdx.y * 128, n0 = blockIdx.x * 128;

    const int c_ = tid & 7, r_ = tid >> 3;
    const uint32_t swz = (uint32_t)((c_ ^ (r_ & 7)) << 4);

    auto load_stage = [&](int c) {
        const uint32_t ab = sb + (uint32_t)(c & 1) * 16384u;
        const uint32_t bb = sb + 32768u + (uint32_t)(c & 1) * 16384u;
        const int k0 = c * 64;
#pragma unroll
        for (int i = 0; i < 4; ++i) {
            int row = r_ + i * 32;
            cpa16(ab + (uint32_t)row * 128u + swz,
                  X + (size_t)(m0 + row) * EMB + k0 + c_ * 8);
            cpa16(bb + (uint32_t)row * 128u + swz,
                  W + (size_t)(n0 + row) * EMB + k0 + c_ * 8);
        }
    };

    float acc[4][4][4];
#pragma unroll
    for (int mt = 0; mt < 4; ++mt)
#pragma unroll
        for (int nt = 0; nt < 4; ++nt)
#pragma unroll
            for (int c = 0; c < 4; ++c) acc[mt][nt][c] = 0.f;

    const int sr  = (lane & 7) + (((lane >> 3) & 1) << 3);
    const int e   = lane >> 4;
    const int sbr = (lane & 7) + ((lane >> 4) << 3);
    const int eb  = (lane >> 3) & 1;

    load_stage(0); cp_commit();
    for (int kt = 0; kt < 16; ++kt) {
        const int buf = kt & 1;
        if (kt + 1 < 16) load_stage(kt + 1);
        cp_commit();
        cp_wait<1>();
        __syncthreads();
        const uint32_t ab = sb + (uint32_t)buf * 16384u;
        const uint32_t bb = sb + 32768u + (uint32_t)buf * 16384u;
#pragma unroll
        for (int ks = 0; ks < 4; ++ks) {
            uint32_t afr[4][4];
#pragma unroll
            for (int mt = 0; mt < 4; ++mt) {
                int row = wm + mt * 16 + sr;
                ldsm4(afr[mt], ab + (uint32_t)row * 128u +
                               ((uint32_t)((ks * 2 + e) ^ (row & 7)) << 4));
            }
#pragma unroll
            for (int ntp = 0; ntp < 2; ++ntp) {
                int row = wn + ntp * 16 + sbr;
                uint32_t bfr[4];
                ldsm4(bfr, bb + (uint32_t)row * 128u +
                           ((uint32_t)((ks * 2 + eb) ^ (row & 7)) << 4));
#pragma unroll
                for (int mt = 0; mt < 4; ++mt) {
                    mmaH(acc[mt][2 * ntp],     afr[mt], bfr[0], bfr[1]);
                    mmaH(acc[mt][2 * ntp + 1], afr[mt], bfr[2], bfr[3]);
                }
            }
        }
        __syncthreads();
    }

#pragma unroll
    for (int nt = 0; nt < 4; ++nt) {
        int n = n0 + wn + nt * 8 + 2 * j;
        float2 bb2 = *reinterpret_cast<const float2*>(&bias[n]);
#pragma unroll
        for (int mt = 0; mt < 4; ++mt) {
            int m = m0 + wm + mt * 16 + g;
            float v00 = (acc[mt][nt][0] + bb2.x) * scale;
            float v01 = (acc[mt][nt][1] + bb2.y) * scale;
            float v10 = (acc[mt][nt][2] + bb2.x) * scale;
            float v11 = (acc[mt][nt][3] + bb2.y) * scale;
            if (layout == 0) {
                float* Yf = (float*)Y;
                *reinterpret_cast<float2*>(&Yf[(size_t)m * EMB + n]) = make_float2(v00, v01);
                *reinterpret_cast<float2*>(&Yf[(size_t)(m + 8) * EMB + n]) = make_float2(v10, v11);
            } else {
                __half* Yh = (__half*)Y;
                int bI = m >> 11, s = m & 2047, h = n >> 6, d = n & 63;
                if (layout == 2) {
                    size_t base = ((size_t)(bI * HEADS + h) * SEQ + s) * HDIM + d;
                    *reinterpret_cast<__half2*>(&Yh[base]) = __floats2half2_rn(v00, v01);
                    *reinterpret_cast<__half2*>(&Yh[base + 8 * HDIM]) = __floats2half2_rn(v10, v11);
                } else {
                    size_t base = ((size_t)(bI * HEADS + h) * HDIM + d) * SEQ + s;
                    Yh[base]           = __float2half_rn(v00);
                    Yh[base + SEQ]     = __float2half_rn(v01);
                    Yh[base + 8]       = __float2half_rn(v10);
                    Yh[base + SEQ + 8] = __float2half_rn(v11);
                }
            }
        }
    }
}

// ---------------- flash attention: 32 q-rows/warp, 4 warps, 3-stage pipe ----
// smem: Q[128][64h] @0 (16K); stage s: K @16384+s*16384, V @+8192
#define QS_B   0u
#define STG_B  16384u
#define STG_SZ 16384u
#define ATTN_SMEM 65536

__global__ __launch_bounds__(128, 2) void attn_h(
    const __half* __restrict__ Qg, const __half* __restrict__ Kg,
    const __half* __restrict__ Vg, const float* __restrict__ badj,
    __half* __restrict__ outp)
{
    extern __shared__ __align__(1024) char sm8[];
    const uint32_t sb = (uint32_t)__cvta_generic_to_shared(sm8);
    const int tid = threadIdx.x, lane = tid & 31, w = tid >> 5;   // w: 0..3
    const int g = lane >> 2, j = lane & 3;
    const int bh = blockIdx.y, b = bh >> 4, h = bh & 15;
    const int q0 = blockIdx.x * 128;

    const int c_ = tid & 7, r_ = tid >> 3;                        // r_: 0..15
    const uint32_t swz = (uint32_t)((c_ ^ (r_ & 7)) << 4);

    auto load_kv = [&](int t) {
        const uint32_t stb = sb + STG_B + (uint32_t)(t % 3) * STG_SZ;
        const int kn = t * 64;
#pragma unroll
        for (int i = 0; i < 4; ++i) {
            int row = r_ + i * 16;
            cpa16(stb + (uint32_t)row * 128u + swz,
                  Kg + ((size_t)bh * SEQ + kn + row) * HDIM + c_ * 8);
            cpa16(stb + 8192u + (uint32_t)row * 128u + swz,
                  Vg + ((size_t)bh * HDIM + row) * SEQ + kn + c_ * 8);
        }
    };

    // prologue: Q (128 rows, 8/thread) + KV[0]; then KV[1]
#pragma unroll
    for (int i = 0; i < 8; ++i) {
        int row = r_ + i * 16;
        cpa16(sb + QS_B + (uint32_t)row * 128u + swz,
              Qg + ((size_t)bh * SEQ + q0 + row) * HDIM + c_ * 8);
    }
    load_kv(0); cp_commit();
    load_kv(1); cp_commit();

    float o[2][8][4];
    float mrun[2][2], lrun[2][2];
#pragma unroll
    for (int rt = 0; rt < 2; ++rt) {
        mrun[rt][0] = mrun[rt][1] = -1e30f;
        lrun[rt][0] = lrun[rt][1] = 0.f;
#pragma unroll
        for (int nt = 0; nt < 8; ++nt)
#pragma unroll
            for (int c = 0; c < 4; ++c) o[rt][nt][c] = 0.f;
    }

    const int sr  = (lane & 7) + (((lane >> 3) & 1) << 3);
    const int e   = lane >> 4;
    const int sbr = (lane & 7) + ((lane >> 4) << 3);
    const int eb  = (lane >> 3) & 1;

    // badj row pointers for the 4 q-rows this thread owns
    const float* bj[2][2];
#pragma unroll
    for (int rt = 0; rt < 2; ++rt)
#pragma unroll
        for (int r = 0; r < 2; ++r)
            bj[rt][r] = badj +
                (((size_t)b * SEQ + (q0 + w * 32 + rt * 16 + g + r * 8)) << 11) + (j << 4);

    uint32_t qf[2][4][4];   // [row-tile][ks][frag]

    for (int kt = 0; kt < 32; ++kt) {
        const uint32_t stb = sb + STG_B + (uint32_t)(kt % 3) * STG_SZ;

        cp_wait<1>();
        __syncthreads();

        if (kt + 2 < 32) load_kv(kt + 2);
        cp_commit();

        if (kt == 0) {
#pragma unroll
            for (int rt = 0; rt < 2; ++rt) {
                const int arow = w * 32 + rt * 16 + sr;
                const uint32_t qab = sb + QS_B + (uint32_t)arow * 128u;
#pragma unroll
                for (int ks = 0; ks < 4; ++ks)
                    ldsm4(qf[rt][ks], qab + ((uint32_t)((ks * 2 + e) ^ (arow & 7)) << 4));
            }
        }

        // ---- S = Q K^T (B-frags shared across both row-tiles) ----
        float sacc[2][8][4];
#pragma unroll
        for (int rt = 0; rt < 2; ++rt)
#pragma unroll
            for (int nt = 0; nt < 8; ++nt)
#pragma unroll
                for (int c = 0; c < 4; ++c) sacc[rt][nt][c] = 0.f;

#pragma unroll
        for (int ks = 0; ks < 4; ++ks) {
#pragma unroll
            for (int ntp = 0; ntp < 4; ++ntp) {
                int row = ntp * 16 + sbr;
                uint32_t bf[4];
                ldsm4(bf, stb + (uint32_t)row * 128u +
                          ((uint32_t)((ks * 2 + eb) ^ (row & 7)) << 4));
#pragma unroll
                for (int rt = 0; rt < 2; ++rt) {
                    mmaH(sacc[rt][2 * ntp],     qf[rt][ks], bf[0], bf[1]);
                    mmaH(sacc[rt][2 * ntp + 1], qf[rt][ks], bf[2], bf[3]);
                }
            }
        }

        // ---- online softmax ----
        uint32_t pf[2][4][4];
#pragma unroll
        for (int rt = 0; rt < 2; ++rt) {
#pragma unroll
            for (int r = 0; r < 2; ++r) {
                const float* bp = bj[rt][r] + (kt << 6);
                float va[16];
                *reinterpret_cast<float4*>(&va[0])  = *reinterpret_cast<const float4*>(bp);
                *reinterpret_cast<float4*>(&va[4])  = *reinterpret_cast<const float4*>(bp + 4);
                *reinterpret_cast<float4*>(&va[8])  = *reinterpret_cast<const float4*>(bp + 8);
                *reinterpret_cast<float4*>(&va[12]) = *reinterpret_cast<const float4*>(bp + 12);
                float rowm = mrun[rt][r];
                float vv[8][2];
#pragma unroll
                for (int nt = 0; nt < 8; ++nt) {
                    float s0 = sacc[rt][nt][r * 2]     + va[nt * 2];
                    float s1 = sacc[rt][nt][r * 2 + 1] + va[nt * 2 + 1];
                    vv[nt][0] = s0; vv[nt][1] = s1;
                    rowm = fmaxf(rowm, fmaxf(s0, s1));
                }
                rowm = fmaxf(rowm, __shfl_xor_sync(0xffffffffu, rowm, 1));
                rowm = fmaxf(rowm, __shfl_xor_sync(0xffffffffu, rowm, 2));
                float rs = 0.f;
#pragma unroll
                for (int nt = 0; nt < 8; ++nt) {
                    float p0 = __expf(vv[nt][0] - rowm);
                    float p1 = __expf(vv[nt][1] - rowm);
                    rs += p0 + p1;
                    pf[rt][nt >> 1][((nt & 1) << 1) | r] = pack_h2(p0, p1);
                }
                rs += __shfl_xor_sync(0xffffffffu, rs, 1);
                rs += __shfl_xor_sync(0xffffffffu, rs, 2);
                float al = __expf(mrun[rt][r] - rowm);
                mrun[rt][r] = rowm;
                lrun[rt][r] = lrun[rt][r] * al + rs;
#pragma unroll
                for (int nt = 0; nt < 8; ++nt) {
                    o[rt][nt][2 * r] *= al; o[rt][nt][2 * r + 1] *= al;
                }
            }
        }

        // ---- O += P V (V-frags shared across both row-tiles) ----
        const uint32_t vb = stb + 8192u;
#pragma unroll
        for (int t = 0; t < 4; ++t) {
#pragma unroll
            for (int ntp = 0; ntp < 4; ++ntp) {
                int row = ntp * 16 + sbr;
                uint32_t bf[4];
                ldsm4(bf, vb + (uint32_t)row * 128u +
                          ((uint32_t)((t * 2 + eb) ^ (row & 7)) << 4));
#pragma unroll
                for (int rt = 0; rt < 2; ++rt) {
                    mmaH(o[rt][2 * ntp],     pf[rt][t], bf[0], bf[1]);
                    mmaH(o[rt][2 * ntp + 1], pf[rt][t], bf[2], bf[3]);
                }
            }
        }
    }

    // epilogue: 4 q-rows per thread
#pragma unroll
    for (int rt = 0; rt < 2; ++rt) {
        const float inv0 = 1.f / lrun[rt][0], inv1 = 1.f / lrun[rt][1];
        const int qa = q0 + w * 32 + rt * 16 + g;
#pragma unroll
        for (int nt = 0; nt < 8; ++nt) {
            int dcol = h * HDIM + nt * 8 + 2 * j;
            *reinterpret_cast<__half2*>(&outp[((size_t)b * SEQ + qa) * EMB + dcol]) =
                __floats2half2_rn(o[rt][nt][0] * inv0, o[rt][nt][1] * inv0);
            *reinterpret_cast<__half2*>(&outp[((size_t)b * SEQ + qa + 8) * EMB + dcol]) =
                __floats2half2_rn(o[rt][nt][2] * inv1, o[rt][nt][3] * inv1);
        }
    }
}

// ---------------- launch -----------------------------------------------------
extern "C" void kernel_launch(void* const* d_in, const int* in_sizes, int n_in,
                              void* d_out, int out_size)
{
    const float* query = (const float*)d_in[0];
    const float* key   = (const float*)d_in[1];
    const float* value = (const float*)d_in[2];
    const float* adj   = (const float*)d_in[3];
    const int*   mask  = (const int*)d_in[4];
    const float* Wq = (const float*)d_in[5];
    const float* bq = (const float*)d_in[6];
    const float* Wk = (const float*)d_in[7];
    const float* bk = (const float*)d_in[8];
    const float* Wv = (const float*)d_in[9];
    const float* bv = (const float*)d_in[10];
    const float* Wo = (const float*)d_in[11];
    const float* bo = (const float*)d_in[12];

    __half *xq, *xk, *xv, *wq, *wk, *wv, *wo, *qq, *kk, *vv, *at;
    float* badj;
    cudaGetSymbolAddress((void**)&xq, g_xq);
    cudaGetSymbolAddress((void**)&xk, g_xk);
    cudaGetSymbolAddress((void**)&xv, g_xv);
    cudaGetSymbolAddress((void**)&wq, g_wq);
    cudaGetSymbolAddress((void**)&wk, g_wk);
    cudaGetSymbolAddress((void**)&wv, g_wv);
    cudaGetSymbolAddress((void**)&wo, g_wo);
    cudaGetSymbolAddress((void**)&qq, g_q);
    cudaGetSymbolAddress((void**)&kk, g_k);
    cudaGetSymbolAddress((void**)&vv, g_v);
    cudaGetSymbolAddress((void**)&at, g_attn);
    cudaGetSymbolAddress((void**)&badj, g_badj);

    cudaFuncSetAttribute(attn_h, cudaFuncAttributeMaxDynamicSharedMemorySize, ATTN_SMEM);
    cudaFuncSetAttribute(gemm_h, cudaFuncAttributeMaxDynamicSharedMemorySize, GEMM_SMEM);

    CvtBatch cb;
    cb.s[0] = (const float4*)query; cb.d[0] = (__half2*)xq; cb.n4[0] = ROWS * EMB / 4;
    cb.s[1] = (const float4*)key;   cb.d[1] = (__half2*)xk; cb.n4[1] = ROWS * EMB / 4;
    cb.s[2] = (const float4*)value; cb.d[2] = (__half2*)xv; cb.n4[2] = ROWS * EMB / 4;
    cb.s[3] = (const float4*)Wq;    cb.d[3] = (__half2*)wq; cb.n4[3] = EMB * EMB / 4;
    cb.s[4] = (const float4*)Wk;    cb.d[4] = (__half2*)wk; cb.n4[4] = EMB * EMB / 4;
    cb.s[5] = (const float4*)Wv;    cb.d[5] = (__half2*)wv; cb.n4[5] = EMB * EMB / 4;
    cb.s[6] = (const float4*)Wo;    cb.d[6] = (__half2*)wo; cb.n4[6] = EMB * EMB / 4;
    cvt_batch_k<<<dim3(1024, 7), 256>>>(cb);
    make_badj_k<<<(BATCH * SEQ * SEQ) / 256, 256>>>(adj, mask, badj);

    GemmBatch gqkv;
    gqkv.X[0] = xq; gqkv.W[0] = wq; gqkv.bias[0] = bq; gqkv.Y[0] = qq;
    gqkv.layout[0] = 2; gqkv.scale[0] = 0.125f;
    gqkv.X[1] = xk; gqkv.W[1] = wk; gqkv.bias[1] = bk; gqkv.Y[1] = kk;
    gqkv.layout[1] = 2; gqkv.scale[1] = 1.0f;
    gqkv.X[2] = xv; gqkv.W[2] = wv; gqkv.bias[2] = bv; gqkv.Y[2] = vv;
    gqkv.layout[2] = 1; gqkv.scale[2] = 1.0f;
    gemm_h<<<dim3(EMB / 128, ROWS / 128, 3), 256, GEMM_SMEM>>>(gqkv);

    attn_h<<<dim3(SEQ / 128, BH), 128, ATTN_SMEM>>>(qq, kk, vv, badj, at);

    GemmBatch go;
    go.X[0] = at; go.W[0] = wo; go.bias[0] = bo; go.Y[0] = d_out;
    go.layout[0] = 0; go.scale[0] = 1.0f;
    go.X[1] = at; go.W[1] = wo; go.bias[1] = bo; go.Y[1] = d_out;
    go.layout[1] = 0; go.scale[1] = 1.0f;
    go.X[2] = at; go.W[2] = wo; go.bias[2] = bo; go.Y[2] = d_out;
    go.layout[2] = 0; go.scale[2] = 1.0f;
    gemm_h<<<dim3(EMB / 128, ROWS / 128, 1), 256, GEMM_SMEM>>>(go);
}

// round 11
// speedup vs baseline: 1.1461x; 1.1461x over previous
#include <cuda_runtime.h>
#include <cuda_fp16.h>
#include <cstdint>

#define BATCH 2
#define SEQ   2048
#define EMB   1024
#define HEADS 16
#define HDIM  64
#define BH    (BATCH*HEADS)
#define ROWS  (BATCH*SEQ)

// ---------------- scratch ----------------------------------------------------
__device__ __half g_xq[ROWS * EMB];
__device__ __half g_xk[ROWS * EMB];
__device__ __half g_xv[ROWS * EMB];
__device__ __half g_wq[EMB * EMB];
__device__ __half g_wk[EMB * EMB];
__device__ __half g_wv[EMB * EMB];
__device__ __half g_wo[EMB * EMB];
__device__ __half g_q[BH * SEQ * HDIM];    // [bh][s][d], pre-scaled 1/8
__device__ __half g_k[BH * SEQ * HDIM];    // [bh][s][d]
__device__ __half g_v[BH * HDIM * SEQ];    // [bh][d][s]
__device__ __half g_attn[ROWS * EMB];      // [b*S+s][h*64+d]
__device__ __half g_badj[BATCH * SEQ * SEQ];  // mask-fused adj (half), tile-permuted

#define MASK_NEG (-60000.0f)

// ---------------- helpers ---------------------------------------------------
__device__ __forceinline__ uint32_t pack_h2(float lo, float hi) {
    uint32_t r;
    asm("cvt.rn.f16x2.f32 %0, %1, %2;" : "=r"(r) : "f"(hi), "f"(lo));
    return r;
}
__device__ __forceinline__ void mmaH(float* d, const uint32_t* a, uint32_t b0, uint32_t b1) {
    asm volatile(
        "mma.sync.aligned.m16n8k16.row.col.f32.f16.f16.f32 "
        "{%0,%1,%2,%3}, {%4,%5,%6,%7}, {%8,%9}, {%0,%1,%2,%3};"
        : "+f"(d[0]), "+f"(d[1]), "+f"(d[2]), "+f"(d[3])
        : "r"(a[0]), "r"(a[1]), "r"(a[2]), "r"(a[3]), "r"(b0), "r"(b1));
}
__device__ __forceinline__ void ldsm4(uint32_t* r, uint32_t addr) {
    asm volatile("ldmatrix.sync.aligned.m8n8.x4.shared.b16 {%0,%1,%2,%3}, [%4];"
                 : "=r"(r[0]), "=r"(r[1]), "=r"(r[2]), "=r"(r[3]) : "r"(addr));
}
__device__ __forceinline__ void cpa16(uint32_t dst, const void* src) {
    asm volatile("cp.async.cg.shared.global [%0], [%1], 16;" :: "r"(dst), "l"(src));
}
__device__ __forceinline__ void cp_commit() { asm volatile("cp.async.commit_group;"); }
template<int N> __device__ __forceinline__ void cp_wait() {
    asm volatile("cp.async.wait_group %0;" :: "n"(N));
}

// ---------------- pre-pass ---------------------------------------------------
struct CvtBatch { const float4* s[7]; __half2* d[7]; int n4[7]; };
__global__ void cvt_batch_k(CvtBatch a) {
    const float4* s = a.s[blockIdx.y];
    __half2* d = a.d[blockIdx.y];
    int n = a.n4[blockIdx.y];
    for (int i = blockIdx.x * 256 + threadIdx.x; i < n; i += gridDim.x * 256) {
        float4 v = s[i];
        d[2 * i]     = __floats2half2_rn(v.x, v.y);
        d[2 * i + 1] = __floats2half2_rn(v.z, v.w);
    }
}

// badj half2 writer: pair index p2 = j*8 + nt  <->  k pair base = nt*8 + 2j
__global__ void make_badj_k(const float* __restrict__ adj, const int* __restrict__ mask,
                            __half2* __restrict__ out) {
    int idx = blockIdx.x * 256 + threadIdx.x;      // [0, B*S*S/2)
    int p2 = idx & 31;
    int base = idx >> 5;                           // (b*S+q)*32 + kt
    int kt = base & 31;
    int q  = (base >> 5) & 2047;
    int b  = base >> 16;
    int jj = p2 >> 3, nt = p2 & 7;
    int k = kt * 64 + nt * 8 + 2 * jj;
    float2 v = *reinterpret_cast<const float2*>(&adj[(size_t)q * SEQ + k]);
    int2 m = *reinterpret_cast<const int2*>(&mask[((size_t)b * SEQ + q) * SEQ + k]);
    out[idx] = __floats2half2_rn(m.x ? v.x : MASK_NEG, m.y ? v.y : MASK_NEG);
}

// ---------------- fp16 GEMM (unchanged) --------------------------------------
#define GEMM_SMEM 65536

struct GemmBatch {
    const __half* X[3]; const __half* W[3]; const float* bias[3];
    void* Y[3]; int layout[3]; float scale[3];
};

__global__ __launch_bounds__(256, 2) void gemm_h(GemmBatch args)
{
    extern __shared__ __align__(1024) char smem[];
    const uint32_t sb = (uint32_t)__cvta_generic_to_shared(smem);
    const int z = blockIdx.z;
    const __half* __restrict__ X = args.X[z];
    const __half* __restrict__ W = args.W[z];
    const float* __restrict__ bias = args.bias[z];
    void* Y = args.Y[z];
    const int layout = args.layout[z];
    const float scale = args.scale[z];

    const int tid = threadIdx.x, lane = tid & 31, wid = tid >> 5;
    const int g = lane >> 2, j = lane & 3;
    const int wm = (wid & 1) * 64, wn = (wid >> 1) * 32;
    const int m0 = blockIdx.y * 128, n0 = blockIdx.x * 128;

    const int c_ = tid & 7, r_ = tid >> 3;
    const uint32_t swz = (uint32_t)((c_ ^ (r_ & 7)) << 4);

    auto load_stage = [&](int c) {
        const uint32_t ab = sb + (uint32_t)(c & 1) * 16384u;
        const uint32_t bb = sb + 32768u + (uint32_t)(c & 1) * 16384u;
        const int k0 = c * 64;
#pragma unroll
        for (int i = 0; i < 4; ++i) {
            int row = r_ + i * 32;
            cpa16(ab + (uint32_t)row * 128u + swz,
                  X + (size_t)(m0 + row) * EMB + k0 + c_ * 8);
            cpa16(bb + (uint32_t)row * 128u + swz,
                  W + (size_t)(n0 + row) * EMB + k0 + c_ * 8);
        }
    };

    float acc[4][4][4];
#pragma unroll
    for (int mt = 0; mt < 4; ++mt)
#pragma unroll
        for (int nt = 0; nt < 4; ++nt)
#pragma unroll
            for (int c = 0; c < 4; ++c) acc[mt][nt][c] = 0.f;

    const int sr  = (lane & 7) + (((lane >> 3) & 1) << 3);
    const int e   = lane >> 4;
    const int sbr = (lane & 7) + ((lane >> 4) << 3);
    const int eb  = (lane >> 3) & 1;

    load_stage(0); cp_commit();
    for (int kt = 0; kt < 16; ++kt) {
        const int buf = kt & 1;
        if (kt + 1 < 16) load_stage(kt + 1);
        cp_commit();
        cp_wait<1>();
        __syncthreads();
        const uint32_t ab = sb + (uint32_t)buf * 16384u;
        const uint32_t bb = sb + 32768u + (uint32_t)buf * 16384u;
#pragma unroll
        for (int ks = 0; ks < 4; ++ks) {
            uint32_t afr[4][4];
#pragma unroll
            for (int mt = 0; mt < 4; ++mt) {
                int row = wm + mt * 16 + sr;
                ldsm4(afr[mt], ab + (uint32_t)row * 128u +
                               ((uint32_t)((ks * 2 + e) ^ (row & 7)) << 4));
            }
#pragma unroll
            for (int ntp = 0; ntp < 2; ++ntp) {
                int row = wn + ntp * 16 + sbr;
                uint32_t bfr[4];
                ldsm4(bfr, bb + (uint32_t)row * 128u +
                           ((uint32_t)((ks * 2 + eb) ^ (row & 7)) << 4));
#pragma unroll
                for (int mt = 0; mt < 4; ++mt) {
                    mmaH(acc[mt][2 * ntp],     afr[mt], bfr[0], bfr[1]);
                    mmaH(acc[mt][2 * ntp + 1], afr[mt], bfr[2], bfr[3]);
                }
            }
        }
        __syncthreads();
    }

#pragma unroll
    for (int nt = 0; nt < 4; ++nt) {
        int n = n0 + wn + nt * 8 + 2 * j;
        float2 bb2 = *reinterpret_cast<const float2*>(&bias[n]);
#pragma unroll
        for (int mt = 0; mt < 4; ++mt) {
            int m = m0 + wm + mt * 16 + g;
            float v00 = (acc[mt][nt][0] + bb2.x) * scale;
            float v01 = (acc[mt][nt][1] + bb2.y) * scale;
            float v10 = (acc[mt][nt][2] + bb2.x) * scale;
            float v11 = (acc[mt][nt][3] + bb2.y) * scale;
            if (layout == 0) {
                float* Yf = (float*)Y;
                *reinterpret_cast<float2*>(&Yf[(size_t)m * EMB + n]) = make_float2(v00, v01);
                *reinterpret_cast<float2*>(&Yf[(size_t)(m + 8) * EMB + n]) = make_float2(v10, v11);
            } else {
                __half* Yh = (__half*)Y;
                int bI = m >> 11, s = m & 2047, h = n >> 6, d = n & 63;
                if (layout == 2) {
                    size_t base = ((size_t)(bI * HEADS + h) * SEQ + s) * HDIM + d;
                    *reinterpret_cast<__half2*>(&Yh[base]) = __floats2half2_rn(v00, v01);
                    *reinterpret_cast<__half2*>(&Yh[base + 8 * HDIM]) = __floats2half2_rn(v10, v11);
                } else {
                    size_t base = ((size_t)(bI * HEADS + h) * HDIM + d) * SEQ + s;
                    Yh[base]           = __float2half_rn(v00);
                    Yh[base + SEQ]     = __float2half_rn(v01);
                    Yh[base + 8]       = __float2half_rn(v10);
                    Yh[base + SEQ + 8] = __float2half_rn(v11);
                }
            }
        }
    }
}

// ---------------- flash attention: R9 base + half badj, prefetched ----------
#define QS_B   0u
#define STG_B  16384u
#define STG_SZ 16384u
#define ATTN_SMEM 65536

__global__ __launch_bounds__(256, 2) void attn_h(
    const __half* __restrict__ Qg, const __half* __restrict__ Kg,
    const __half* __restrict__ Vg, const __half* __restrict__ badj,
    __half* __restrict__ outp)
{
    extern __shared__ __align__(1024) char sm8[];
    const uint32_t sb = (uint32_t)__cvta_generic_to_shared(sm8);
    const int tid = threadIdx.x, lane = tid & 31, w = tid >> 5;
    const int g = lane >> 2, j = lane & 3;
    const int bh = blockIdx.y, b = bh >> 4, h = bh & 15;
    const int q0 = blockIdx.x * 128;

    const int c_ = tid & 7, r_ = tid >> 3;
    const uint32_t swz = (uint32_t)((c_ ^ (r_ & 7)) << 4);

    auto load_kv = [&](int t) {
        const uint32_t stb = sb + STG_B + (uint32_t)(t % 3) * STG_SZ;
        const int kn = t * 64;
#pragma unroll
        for (int i = 0; i < 2; ++i) {
            int row = r_ + i * 32;
            cpa16(stb + (uint32_t)row * 128u + swz,
                  Kg + ((size_t)bh * SEQ + kn + row) * HDIM + c_ * 8);
            cpa16(stb + 8192u + (uint32_t)row * 128u + swz,
                  Vg + ((size_t)bh * HDIM + row) * SEQ + kn + c_ * 8);
        }
    };

#pragma unroll
    for (int i = 0; i < 4; ++i) {
        int row = r_ + i * 32;
        cpa16(sb + QS_B + (uint32_t)row * 128u + swz,
              Qg + ((size_t)bh * SEQ + q0 + row) * HDIM + c_ * 8);
    }
    load_kv(0); cp_commit();
    load_kv(1); cp_commit();

    float o[8][4];
    float mrun[2] = {-1e30f, -1e30f}, lrun[2] = {0.f, 0.f};
#pragma unroll
    for (int nt = 0; nt < 8; ++nt)
#pragma unroll
        for (int c = 0; c < 4; ++c) o[nt][c] = 0.f;

    const int sr  = (lane & 7) + (((lane >> 3) & 1) << 3);
    const int e   = lane >> 4;
    const int sbr = (lane & 7) + ((lane >> 4) << 3);
    const int eb  = (lane >> 3) & 1;
    const int arow = w * 16 + sr;
    const uint32_t qab = sb + QS_B + (uint32_t)arow * 128u;

    // badj rows (half, tile-permuted, j-grouped: 16 halfs per (row, tile, j))
    const __half* bj0 = badj + (((size_t)b * SEQ + (q0 + w * 16 + g)) << 11) + (j << 4);
    const __half* bj1 = badj + (((size_t)b * SEQ + (q0 + w * 16 + g + 8)) << 11) + (j << 4);

    uint32_t qf[4][4];

    for (int kt = 0; kt < 32; ++kt) {
        const uint32_t stb = sb + STG_B + (uint32_t)(kt % 3) * STG_SZ;

        cp_wait<1>();
        __syncthreads();

        if (kt + 2 < 32) load_kv(kt + 2);
        cp_commit();

        // ---- prefetch badj for this tile (hidden under QK mma) ----
        uint32_t pb[2][8];
#pragma unroll
        for (int r = 0; r < 2; ++r) {
            const __half* bp = (r ? bj1 : bj0) + (kt << 6);
            uint4 u0 = *reinterpret_cast<const uint4*>(bp);
            uint4 u1 = *reinterpret_cast<const uint4*>(bp + 8);
            pb[r][0] = u0.x; pb[r][1] = u0.y; pb[r][2] = u0.z; pb[r][3] = u0.w;
            pb[r][4] = u1.x; pb[r][5] = u1.y; pb[r][6] = u1.z; pb[r][7] = u1.w;
        }

        if (kt == 0) {
#pragma unroll
            for (int ks = 0; ks < 4; ++ks)
                ldsm4(qf[ks], qab + ((uint32_t)((ks * 2 + e) ^ (arow & 7)) << 4));
        }

        // ---- S = Q K^T ----
        float sacc[8][4];
#pragma unroll
        for (int nt = 0; nt < 8; ++nt)
#pragma unroll
            for (int c = 0; c < 4; ++c) sacc[nt][c] = 0.f;

#pragma unroll
        for (int ks = 0; ks < 4; ++ks) {
#pragma unroll
            for (int ntp = 0; ntp < 4; ++ntp) {
                int row = ntp * 16 + sbr;
                uint32_t bf[4];
                ldsm4(bf, stb + (uint32_t)row * 128u +
                          ((uint32_t)((ks * 2 + eb) ^ (row & 7)) << 4));
                mmaH(sacc[2 * ntp],     qf[ks], bf[0], bf[1]);
                mmaH(sacc[2 * ntp + 1], qf[ks], bf[2], bf[3]);
            }
        }

        // ---- online softmax (badj from prefetched half2 regs) ----
        uint32_t pf[4][4];
#pragma unroll
        for (int r = 0; r < 2; ++r) {
            float rowm = mrun[r];
            float vv[8][2];
#pragma unroll
            for (int nt = 0; nt < 8; ++nt) {
                float2 ad = __half22float2(*reinterpret_cast<__half2*>(&pb[r][nt]));
                float s0 = sacc[nt][r * 2]     + ad.x;
                float s1 = sacc[nt][r * 2 + 1] + ad.y;
                vv[nt][0] = s0; vv[nt][1] = s1;
                rowm = fmaxf(rowm, fmaxf(s0, s1));
            }
            rowm = fmaxf(rowm, __shfl_xor_sync(0xffffffffu, rowm, 1));
            rowm = fmaxf(rowm, __shfl_xor_sync(0xffffffffu, rowm, 2));
            float rs = 0.f;
#pragma unroll
            for (int nt = 0; nt < 8; ++nt) {
                float p0 = __expf(vv[nt][0] - rowm);
                float p1 = __expf(vv[nt][1] - rowm);
                rs += p0 + p1;
                pf[nt >> 1][((nt & 1) << 1) | r] = pack_h2(p0, p1);
            }
            rs += __shfl_xor_sync(0xffffffffu, rs, 1);
            rs += __shfl_xor_sync(0xffffffffu, rs, 2);
            float al = __expf(mrun[r] - rowm);
            mrun[r] = rowm;
            lrun[r] = lrun[r] * al + rs;
#pragma unroll
            for (int nt = 0; nt < 8; ++nt) { o[nt][2 * r] *= al; o[nt][2 * r + 1] *= al; }
        }

        // ---- O += P V ----
        const uint32_t vb = stb + 8192u;
#pragma unroll
        for (int t = 0; t < 4; ++t) {
#pragma unroll
            for (int ntp = 0; ntp < 4; ++ntp) {
                int row = ntp * 16 + sbr;
                uint32_t bf[4];
                ldsm4(bf, vb + (uint32_t)row * 128u +
                          ((uint32_t)((t * 2 + eb) ^ (row & 7)) << 4));
                mmaH(o[2 * ntp],     pf[t], bf[0], bf[1]);
                mmaH(o[2 * ntp + 1], pf[t], bf[2], bf[3]);
            }
        }
    }

    // epilogue
    const float inv0 = 1.f / lrun[0], inv1 = 1.f / lrun[1];
    const int qa = q0 + w * 16 + g;
#pragma unroll
    for (int nt = 0; nt < 8; ++nt) {
        int dcol = h * HDIM + nt * 8 + 2 * j;
        *reinterpret_cast<__half2*>(&outp[((size_t)b * SEQ + qa) * EMB + dcol]) =
            __floats2half2_rn(o[nt][0] * inv0, o[nt][1] * inv0);
        *reinterpret_cast<__half2*>(&outp[((size_t)b * SEQ + qa + 8) * EMB + dcol]) =
            __floats2half2_rn(o[nt][2] * inv1, o[nt][3] * inv1);
    }
}

// ---------------- launch -----------------------------------------------------
extern "C" void kernel_launch(void* const* d_in, const int* in_sizes, int n_in,
                              void* d_out, int out_size)
{
    const float* query = (const float*)d_in[0];
    const float* key   = (const float*)d_in[1];
    const float* value = (const float*)d_in[2];
    const float* adj   = (const float*)d_in[3];
    const int*   mask  = (const int*)d_in[4];
    const float* Wq = (const float*)d_in[5];
    const float* bq = (const float*)d_in[6];
    const float* Wk = (const float*)d_in[7];
    const float* bk = (const float*)d_in[8];
    const float* Wv = (const float*)d_in[9];
    const float* bv = (const float*)d_in[10];
    const float* Wo = (const float*)d_in[11];
    const float* bo = (const float*)d_in[12];

    __half *xq, *xk, *xv, *wq, *wk, *wv, *wo, *qq, *kk, *vv, *at, *badj;
    cudaGetSymbolAddress((void**)&xq, g_xq);
    cudaGetSymbolAddress((void**)&xk, g_xk);
    cudaGetSymbolAddress((void**)&xv, g_xv);
    cudaGetSymbolAddress((void**)&wq, g_wq);
    cudaGetSymbolAddress((void**)&wk, g_wk);
    cudaGetSymbolAddress((void**)&wv, g_wv);
    cudaGetSymbolAddress((void**)&wo, g_wo);
    cudaGetSymbolAddress((void**)&qq, g_q);
    cudaGetSymbolAddress((void**)&kk, g_k);
    cudaGetSymbolAddress((void**)&vv, g_v);
    cudaGetSymbolAddress((void**)&at, g_attn);
    cudaGetSymbolAddress((void**)&badj, g_badj);

    cudaFuncSetAttribute(attn_h, cudaFuncAttributeMaxDynamicSharedMemorySize, ATTN_SMEM);
    cudaFuncSetAttribute(gemm_h, cudaFuncAttributeMaxDynamicSharedMemorySize, GEMM_SMEM);

    CvtBatch cb;
    cb.s[0] = (const float4*)query; cb.d[0] = (__half2*)xq; cb.n4[0] = ROWS * EMB / 4;
    cb.s[1] = (const float4*)key;   cb.d[1] = (__half2*)xk; cb.n4[1] = ROWS * EMB / 4;
    cb.s[2] = (const float4*)value; cb.d[2] = (__half2*)xv; cb.n4[2] = ROWS * EMB / 4;
    cb.s[3] = (const float4*)Wq;    cb.d[3] = (__half2*)wq; cb.n4[3] = EMB * EMB / 4;
    cb.s[4] = (const float4*)Wk;    cb.d[4] = (__half2*)wk; cb.n4[4] = EMB * EMB / 4;
    cb.s[5] = (const float4*)Wv;    cb.d[5] = (__half2*)wv; cb.n4[5] = EMB * EMB / 4;
    cb.s[6] = (const float4*)Wo;    cb.d[6] = (__half2*)wo; cb.n4[6] = EMB * EMB / 4;
    cvt_batch_k<<<dim3(1024, 7), 256>>>(cb);
    make_badj_k<<<(BATCH * SEQ * SEQ / 2) / 256, 256>>>(adj, mask, (__half2*)badj);

    GemmBatch gqkv;
    gqkv.X[0] = xq; gqkv.W[0] = wq; gqkv.bias[0] = bq; gqkv.Y[0] = qq;
    gqkv.layout[0] = 2; gqkv.scale[0] = 0.125f;
    gqkv.X[1] = xk; gqkv.W[1] = wk; gqkv.bias[1] = bk; gqkv.Y[1] = kk;
    gqkv.layout[1] = 2; gqkv.scale[1] = 1.0f;
    gqkv.X[2] = xv; gqkv.W[2] = wv; gqkv.bias[2] = bv; gqkv.Y[2] = vv;
    gqkv.layout[2] = 1; gqkv.scale[2] = 1.0f;
    gemm_h<<<dim3(EMB / 128, ROWS / 128, 3), 256, GEMM_SMEM>>>(gqkv);

    attn_h<<<dim3(SEQ / 128, BH), 256, ATTN_SMEM>>>(qq, kk, vv, badj, at);

    GemmBatch go;
    go.X[0] = at; go.W[0] = wo; go.bias[0] = bo; go.Y[0] = d_out;
    go.layout[0] = 0; go.scale[0] = 1.0f;
    go.X[1] = at; go.W[1] = wo; go.bias[1] = bo; go.Y[1] = d_out;
    go.layout[1] = 0; go.scale[1] = 1.0f;
    go.X[2] = at; go.W[2] = wo; go.bias[2] = bo; go.Y[2] = d_out;
    go.layout[2] = 0; go.scale[2] = 1.0f;
    gemm_h<<<dim3(EMB / 128, ROWS / 128, 1), 256, GEMM_SMEM>>>(go);
}

// round 12
// speedup vs baseline: 1.2135x; 1.0588x over previous
#include <cuda_runtime.h>
#include <cuda_fp16.h>
#include <cstdint>

#define BATCH 2
#define SEQ   2048
#define EMB   1024
#define HEADS 16
#define HDIM  64
#define BH    (BATCH*HEADS)
#define ROWS  (BATCH*SEQ)

#define LOG2E 1.44269504f
#define MASK_NEG (-60000.0f)

// ---------------- scratch ----------------------------------------------------
__device__ __half g_xq[ROWS * EMB];
__device__ __half g_xk[ROWS * EMB];
__device__ __half g_xv[ROWS * EMB];
__device__ __half g_wq[EMB * EMB];
__device__ __half g_wk[EMB * EMB];
__device__ __half g_wv[EMB * EMB];
__device__ __half g_wo[EMB * EMB];
__device__ __half g_q[BH * SEQ * HDIM];    // [bh][s][d], pre-scaled log2e/8
__device__ __half g_k[BH * SEQ * HDIM];    // [bh][s][d]
__device__ __half g_v[BH * HDIM * SEQ];    // [bh][d][s]
__device__ __half g_attn[ROWS * EMB];      // [b*S+s][h*64+d]
__device__ __half g_badj[BATCH * SEQ * SEQ];  // (mask?adj*log2e:-60000), tile-permuted

// ---------------- helpers ---------------------------------------------------
__device__ __forceinline__ uint32_t pack_h2(float lo, float hi) {
    uint32_t r;
    asm("cvt.rn.f16x2.f32 %0, %1, %2;" : "=r"(r) : "f"(hi), "f"(lo));
    return r;
}
__device__ __forceinline__ float ex2(float x) {
    float y;
    asm("ex2.approx.ftz.f32 %0, %1;" : "=f"(y) : "f"(x));
    return y;
}
__device__ __forceinline__ void mmaH(float* d, const uint32_t* a, uint32_t b0, uint32_t b1) {
    asm volatile(
        "mma.sync.aligned.m16n8k16.row.col.f32.f16.f16.f32 "
        "{%0,%1,%2,%3}, {%4,%5,%6,%7}, {%8,%9}, {%0,%1,%2,%3};"
        : "+f"(d[0]), "+f"(d[1]), "+f"(d[2]), "+f"(d[3])
        : "r"(a[0]), "r"(a[1]), "r"(a[2]), "r"(a[3]), "r"(b0), "r"(b1));
}
__device__ __forceinline__ void ldsm4(uint32_t* r, uint32_t addr) {
    asm volatile("ldmatrix.sync.aligned.m8n8.x4.shared.b16 {%0,%1,%2,%3}, [%4];"
                 : "=r"(r[0]), "=r"(r[1]), "=r"(r[2]), "=r"(r[3]) : "r"(addr));
}
__device__ __forceinline__ void cpa16(uint32_t dst, const void* src) {
    asm volatile("cp.async.cg.shared.global [%0], [%1], 16;" :: "r"(dst), "l"(src));
}
__device__ __forceinline__ void cp_commit() { asm volatile("cp.async.commit_group;"); }
template<int N> __device__ __forceinline__ void cp_wait() {
    asm volatile("cp.async.wait_group %0;" :: "n"(N));
}

// ---------------- pre-pass ---------------------------------------------------
struct CvtBatch { const float4* s[7]; __half2* d[7]; int n4[7]; };
__global__ void cvt_batch_k(CvtBatch a) {
    const float4* s = a.s[blockIdx.y];
    __half2* d = a.d[blockIdx.y];
    int n = a.n4[blockIdx.y];
    for (int i = blockIdx.x * 256 + threadIdx.x; i < n; i += gridDim.x * 256) {
        float4 v = s[i];
        d[2 * i]     = __floats2half2_rn(v.x, v.y);
        d[2 * i + 1] = __floats2half2_rn(v.z, v.w);
    }
}

// badj half2 writer (log2e-scaled): pair index p2 = j*8 + nt  <->  k = nt*8 + 2j
__global__ void make_badj_k(const float* __restrict__ adj, const int* __restrict__ mask,
                            __half2* __restrict__ out) {
    int idx = blockIdx.x * 256 + threadIdx.x;      // [0, B*S*S/2)
    int p2 = idx & 31;
    int base = idx >> 5;                           // (b*S+q)*32 + kt
    int kt = base & 31;
    int q  = (base >> 5) & 2047;
    int b  = base >> 16;
    int jj = p2 >> 3, nt = p2 & 7;
    int k = kt * 64 + nt * 8 + 2 * jj;
    float2 v = *reinterpret_cast<const float2*>(&adj[(size_t)q * SEQ + k]);
    int2 m = *reinterpret_cast<const int2*>(&mask[((size_t)b * SEQ + q) * SEQ + k]);
    out[idx] = __floats2half2_rn(m.x ? v.x * LOG2E : MASK_NEG,
                                 m.y ? v.y * LOG2E : MASK_NEG);
}

// ---------------- fp16 GEMM (unchanged) --------------------------------------
#define GEMM_SMEM 65536

struct GemmBatch {
    const __half* X[3]; const __half* W[3]; const float* bias[3];
    void* Y[3]; int layout[3]; float scale[3];
};

__global__ __launch_bounds__(256, 2) void gemm_h(GemmBatch args)
{
    extern __shared__ __align__(1024) char smem[];
    const uint32_t sb = (uint32_t)__cvta_generic_to_shared(smem);
    const int z = blockIdx.z;
    const __half* __restrict__ X = args.X[z];
    const __half* __restrict__ W = args.W[z];
    const float* __restrict__ bias = args.bias[z];
    void* Y = args.Y[z];
    const int layout = args.layout[z];
    const float scale = args.scale[z];

    const int tid = threadIdx.x, lane = tid & 31, wid = tid >> 5;
    const int g = lane >> 2, j = lane & 3;
    const int wm = (wid & 1) * 64, wn = (wid >> 1) * 32;
    const int m0 = blockIdx.y * 128, n0 = blockIdx.x * 128;

    const int c_ = tid & 7, r_ = tid >> 3;
    const uint32_t swz = (uint32_t)((c_ ^ (r_ & 7)) << 4);

    auto load_stage = [&](int c) {
        const uint32_t ab = sb + (uint32_t)(c & 1) * 16384u;
        const uint32_t bb = sb + 32768u + (uint32_t)(c & 1) * 16384u;
        const int k0 = c * 64;
#pragma unroll
        for (int i = 0; i < 4; ++i) {
            int row = r_ + i * 32;
            cpa16(ab + (uint32_t)row * 128u + swz,
                  X + (size_t)(m0 + row) * EMB + k0 + c_ * 8);
            cpa16(bb + (uint32_t)row * 128u + swz,
                  W + (size_t)(n0 + row) * EMB + k0 + c_ * 8);
        }
    };

    float acc[4][4][4];
#pragma unroll
    for (int mt = 0; mt < 4; ++mt)
#pragma unroll
        for (int nt = 0; nt < 4; ++nt)
#pragma unroll
            for (int c = 0; c < 4; ++c) acc[mt][nt][c] = 0.f;

    const int sr  = (lane & 7) + (((lane >> 3) & 1) << 3);
    const int e   = lane >> 4;
    const int sbr = (lane & 7) + ((lane >> 4) << 3);
    const int eb  = (lane >> 3) & 1;

    load_stage(0); cp_commit();
    for (int kt = 0; kt < 16; ++kt) {
        const int buf = kt & 1;
        if (kt + 1 < 16) load_stage(kt + 1);
        cp_commit();
        cp_wait<1>();
        __syncthreads();
        const uint32_t ab = sb + (uint32_t)buf * 16384u;
        const uint32_t bb = sb + 32768u + (uint32_t)buf * 16384u;
#pragma unroll
        for (int ks = 0; ks < 4; ++ks) {
            uint32_t afr[4][4];
#pragma unroll
            for (int mt = 0; mt < 4; ++mt) {
                int row = wm + mt * 16 + sr;
                ldsm4(afr[mt], ab + (uint32_t)row * 128u +
                               ((uint32_t)((ks * 2 + e) ^ (row & 7)) << 4));
            }
#pragma unroll
            for (int ntp = 0; ntp < 2; ++ntp) {
                int row = wn + ntp * 16 + sbr;
                uint32_t bfr[4];
                ldsm4(bfr, bb + (uint32_t)row * 128u +
                           ((uint32_t)((ks * 2 + eb) ^ (row & 7)) << 4));
#pragma unroll
                for (int mt = 0; mt < 4; ++mt) {
                    mmaH(acc[mt][2 * ntp],     afr[mt], bfr[0], bfr[1]);
                    mmaH(acc[mt][2 * ntp + 1], afr[mt], bfr[2], bfr[3]);
                }
            }
        }
        __syncthreads();
    }

#pragma unroll
    for (int nt = 0; nt < 4; ++nt) {
        int n = n0 + wn + nt * 8 + 2 * j;
        float2 bb2 = *reinterpret_cast<const float2*>(&bias[n]);
#pragma unroll
        for (int mt = 0; mt < 4; ++mt) {
            int m = m0 + wm + mt * 16 + g;
            float v00 = (acc[mt][nt][0] + bb2.x) * scale;
            float v01 = (acc[mt][nt][1] + bb2.y) * scale;
            float v10 = (acc[mt][nt][2] + bb2.x) * scale;
            float v11 = (acc[mt][nt][3] + bb2.y) * scale;
            if (layout == 0) {
                float* Yf = (float*)Y;
                *reinterpret_cast<float2*>(&Yf[(size_t)m * EMB + n]) = make_float2(v00, v01);
                *reinterpret_cast<float2*>(&Yf[(size_t)(m + 8) * EMB + n]) = make_float2(v10, v11);
            } else {
                __half* Yh = (__half*)Y;
                int bI = m >> 11, s = m & 2047, h = n >> 6, d = n & 63;
                if (layout == 2) {
                    size_t base = ((size_t)(bI * HEADS + h) * SEQ + s) * HDIM + d;
                    *reinterpret_cast<__half2*>(&Yh[base]) = __floats2half2_rn(v00, v01);
                    *reinterpret_cast<__half2*>(&Yh[base + 8 * HDIM]) = __floats2half2_rn(v10, v11);
                } else {
                    size_t base = ((size_t)(bI * HEADS + h) * HDIM + d) * SEQ + s;
                    Yh[base]           = __float2half_rn(v00);
                    Yh[base + SEQ]     = __float2half_rn(v01);
                    Yh[base + 8]       = __float2half_rn(v10);
                    Yh[base + SEQ + 8] = __float2half_rn(v11);
                }
            }
        }
    }
}

// ---------------- flash attention: log2-domain softmax, C-init bias ---------
#define QS_B   0u
#define STG_B  16384u
#define STG_SZ 16384u
#define ATTN_SMEM 65536

__global__ __launch_bounds__(256, 2) void attn_h(
    const __half* __restrict__ Qg, const __half* __restrict__ Kg,
    const __half* __restrict__ Vg, const __half* __restrict__ badj,
    __half* __restrict__ outp)
{
    extern __shared__ __align__(1024) char sm8[];
    const uint32_t sb = (uint32_t)__cvta_generic_to_shared(sm8);
    const int tid = threadIdx.x, lane = tid & 31, w = tid >> 5;
    const int g = lane >> 2, j = lane & 3;
    const int bh = blockIdx.y, b = bh >> 4, h = bh & 15;
    const int q0 = blockIdx.x * 128;

    const int c_ = tid & 7, r_ = tid >> 3;
    const uint32_t swz = (uint32_t)((c_ ^ (r_ & 7)) << 4);

    auto load_kv = [&](int t) {
        const uint32_t stb = sb + STG_B + (uint32_t)(t % 3) * STG_SZ;
        const int kn = t * 64;
#pragma unroll
        for (int i = 0; i < 2; ++i) {
            int row = r_ + i * 32;
            cpa16(stb + (uint32_t)row * 128u + swz,
                  Kg + ((size_t)bh * SEQ + kn + row) * HDIM + c_ * 8);
            cpa16(stb + 8192u + (uint32_t)row * 128u + swz,
                  Vg + ((size_t)bh * HDIM + row) * SEQ + kn + c_ * 8);
        }
    };

#pragma unroll
    for (int i = 0; i < 4; ++i) {
        int row = r_ + i * 32;
        cpa16(sb + QS_B + (uint32_t)row * 128u + swz,
              Qg + ((size_t)bh * SEQ + q0 + row) * HDIM + c_ * 8);
    }
    load_kv(0); cp_commit();
    load_kv(1); cp_commit();

    float o[8][4];
    float mrun[2] = {-1e30f, -1e30f}, lrun[2] = {0.f, 0.f};   // lrun per-lane partial
#pragma unroll
    for (int nt = 0; nt < 8; ++nt)
#pragma unroll
        for (int c = 0; c < 4; ++c) o[nt][c] = 0.f;

    const int sr  = (lane & 7) + (((lane >> 3) & 1) << 3);
    const int e   = lane >> 4;
    const int sbr = (lane & 7) + ((lane >> 4) << 3);
    const int eb  = (lane >> 3) & 1;
    const int arow = w * 16 + sr;
    const uint32_t qab = sb + QS_B + (uint32_t)arow * 128u;

    const __half* bj0 = badj + (((size_t)b * SEQ + (q0 + w * 16 + g)) << 11) + (j << 4);
    const __half* bj1 = badj + (((size_t)b * SEQ + (q0 + w * 16 + g + 8)) << 11) + (j << 4);

    uint32_t qf[4][4];

    for (int kt = 0; kt < 32; ++kt) {
        const uint32_t stb = sb + STG_B + (uint32_t)(kt % 3) * STG_SZ;

        // badj prefetch issued BEFORE the barrier: L2 latency hides under it
        uint32_t pb[2][8];
#pragma unroll
        for (int r = 0; r < 2; ++r) {
            const __half* bp = (r ? bj1 : bj0) + (kt << 6);
            uint4 u0 = *reinterpret_cast<const uint4*>(bp);
            uint4 u1 = *reinterpret_cast<const uint4*>(bp + 8);
            pb[r][0] = u0.x; pb[r][1] = u0.y; pb[r][2] = u0.z; pb[r][3] = u0.w;
            pb[r][4] = u1.x; pb[r][5] = u1.y; pb[r][6] = u1.z; pb[r][7] = u1.w;
        }

        cp_wait<1>();
        __syncthreads();

        if (kt + 2 < 32) load_kv(kt + 2);
        cp_commit();

        if (kt == 0) {
#pragma unroll
            for (int ks = 0; ks < 4; ++ks)
                ldsm4(qf[ks], qab + ((uint32_t)((ks * 2 + e) ^ (arow & 7)) << 4));
        }

        // ---- sacc initialized with badj (mma C-operand does the bias add) ----
        float sacc[8][4];
#pragma unroll
        for (int r = 0; r < 2; ++r)
#pragma unroll
            for (int nt = 0; nt < 8; ++nt) {
                float2 ad = __half22float2(*reinterpret_cast<__half2*>(&pb[r][nt]));
                sacc[nt][r * 2]     = ad.x;
                sacc[nt][r * 2 + 1] = ad.y;
            }

        // ---- S = badj + Q K^T (log2 domain) ----
#pragma unroll
        for (int ks = 0; ks < 4; ++ks) {
#pragma unroll
            for (int ntp = 0; ntp < 4; ++ntp) {
                int row = ntp * 16 + sbr;
                uint32_t bf[4];
                ldsm4(bf, stb + (uint32_t)row * 128u +
                          ((uint32_t)((ks * 2 + eb) ^ (row & 7)) << 4));
                mmaH(sacc[2 * ntp],     qf[ks], bf[0], bf[1]);
                mmaH(sacc[2 * ntp + 1], qf[ks], bf[2], bf[3]);
            }
        }

        // ---- online softmax (exp2, conditional rescale, lazy l-reduce) ----
        uint32_t pf[4][4];
#pragma unroll
        for (int r = 0; r < 2; ++r) {
            float rowm = sacc[0][r * 2];
#pragma unroll
            for (int nt = 0; nt < 8; ++nt)
                rowm = fmaxf(rowm, fmaxf(sacc[nt][r * 2], sacc[nt][r * 2 + 1]));
            rowm = fmaxf(rowm, __shfl_xor_sync(0xffffffffu, rowm, 1));
            rowm = fmaxf(rowm, __shfl_xor_sync(0xffffffffu, rowm, 2));
            const float mn = fmaxf(rowm, mrun[r]);
            if (mn > mrun[r]) {           // max improved: rescale (rare later)
                float al = ex2(mrun[r] - mn);
                lrun[r] *= al;
                mrun[r] = mn;
#pragma unroll
                for (int nt = 0; nt < 8; ++nt) {
                    o[nt][2 * r] *= al; o[nt][2 * r + 1] *= al;
                }
            }
            float rs = 0.f;
#pragma unroll
            for (int nt = 0; nt < 8; ++nt) {
                float p0 = ex2(sacc[nt][r * 2]     - mn);
                float p1 = ex2(sacc[nt][r * 2 + 1] - mn);
                rs += p0 + p1;
                pf[nt >> 1][((nt & 1) << 1) | r] = pack_h2(p0, p1);
            }
            lrun[r] += rs;                // per-lane partial; reduced in epilogue
        }

        // ---- O += P V ----
        const uint32_t vb = stb + 8192u;
#pragma unroll
        for (int t = 0; t < 4; ++t) {
#pragma unroll
            for (int ntp = 0; ntp < 4; ++ntp) {
                int row = ntp * 16 + sbr;
                uint32_t bf[4];
                ldsm4(bf, vb + (uint32_t)row * 128u +
                          ((uint32_t)((t * 2 + eb) ^ (row & 7)) << 4));
                mmaH(o[2 * ntp],     pf[t], bf[0], bf[1]);
                mmaH(o[2 * ntp + 1], pf[t], bf[2], bf[3]);
            }
        }
    }

    // epilogue: quad-reduce l, normalize, store
    float l0 = lrun[0], l1 = lrun[1];
    l0 += __shfl_xor_sync(0xffffffffu, l0, 1);
    l0 += __shfl_xor_sync(0xffffffffu, l0, 2);
    l1 += __shfl_xor_sync(0xffffffffu, l1, 1);
    l1 += __shfl_xor_sync(0xffffffffu, l1, 2);
    const float inv0 = 1.f / l0, inv1 = 1.f / l1;
    const int qa = q0 + w * 16 + g;
#pragma unroll
    for (int nt = 0; nt < 8; ++nt) {
        int dcol = h * HDIM + nt * 8 + 2 * j;
        *reinterpret_cast<__half2*>(&outp[((size_t)b * SEQ + qa) * EMB + dcol]) =
            __floats2half2_rn(o[nt][0] * inv0, o[nt][1] * inv0);
        *reinterpret_cast<__half2*>(&outp[((size_t)b * SEQ + qa + 8) * EMB + dcol]) =
            __floats2half2_rn(o[nt][2] * inv1, o[nt][3] * inv1);
    }
}

// ---------------- launch -----------------------------------------------------
extern "C" void kernel_launch(void* const* d_in, const int* in_sizes, int n_in,
                              void* d_out, int out_size)
{
    const float* query = (const float*)d_in[0];
    const float* key   = (const float*)d_in[1];
    const float* value = (const float*)d_in[2];
    const float* adj   = (const float*)d_in[3];
    const int*   mask  = (const int*)d_in[4];
    const float* Wq = (const float*)d_in[5];
    const float* bq = (const float*)d_in[6];
    const float* Wk = (const float*)d_in[7];
    const float* bk = (const float*)d_in[8];
    const float* Wv = (const float*)d_in[9];
    const float* bv = (const float*)d_in[10];
    const float* Wo = (const float*)d_in[11];
    const float* bo = (const float*)d_in[12];

    __half *xq, *xk, *xv, *wq, *wk, *wv, *wo, *qq, *kk, *vv, *at, *badj;
    cudaGetSymbolAddress((void**)&xq, g_xq);
    cudaGetSymbolAddress((void**)&xk, g_xk);
    cudaGetSymbolAddress((void**)&xv, g_xv);
    cudaGetSymbolAddress((void**)&wq, g_wq);
    cudaGetSymbolAddress((void**)&wk, g_wk);
    cudaGetSymbolAddress((void**)&wv, g_wv);
    cudaGetSymbolAddress((void**)&wo, g_wo);
    cudaGetSymbolAddress((void**)&qq, g_q);
    cudaGetSymbolAddress((void**)&kk, g_k);
    cudaGetSymbolAddress((void**)&vv, g_v);
    cudaGetSymbolAddress((void**)&at, g_attn);
    cudaGetSymbolAddress((void**)&badj, g_badj);

    cudaFuncSetAttribute(attn_h, cudaFuncAttributeMaxDynamicSharedMemorySize, ATTN_SMEM);
    cudaFuncSetAttribute(gemm_h, cudaFuncAttributeMaxDynamicSharedMemorySize, GEMM_SMEM);

    CvtBatch cb;
    cb.s[0] = (const float4*)query; cb.d[0] = (__half2*)xq; cb.n4[0] = ROWS * EMB / 4;
    cb.s[1] = (const float4*)key;   cb.d[1] = (__half2*)xk; cb.n4[1] = ROWS * EMB / 4;
    cb.s[2] = (const float4*)value; cb.d[2] = (__half2*)xv; cb.n4[2] = ROWS * EMB / 4;
    cb.s[3] = (const float4*)Wq;    cb.d[3] = (__half2*)wq; cb.n4[3] = EMB * EMB / 4;
    cb.s[4] = (const float4*)Wk;    cb.d[4] = (__half2*)wk; cb.n4[4] = EMB * EMB / 4;
    cb.s[5] = (const float4*)Wv;    cb.d[5] = (__half2*)wv; cb.n4[5] = EMB * EMB / 4;
    cb.s[6] = (const float4*)Wo;    cb.d[6] = (__half2*)wo; cb.n4[6] = EMB * EMB / 4;
    cvt_batch_k<<<dim3(1024, 7), 256>>>(cb);
    make_badj_k<<<(BATCH * SEQ * SEQ / 2) / 256, 256>>>(adj, mask, (__half2*)badj);

    GemmBatch gqkv;
    gqkv.X[0] = xq; gqkv.W[0] = wq; gqkv.bias[0] = bq; gqkv.Y[0] = qq;
    gqkv.layout[0] = 2; gqkv.scale[0] = 0.125f * LOG2E;   // log2 domain
    gqkv.X[1] = xk; gqkv.W[1] = wk; gqkv.bias[1] = bk; gqkv.Y[1] = kk;
    gqkv.layout[1] = 2; gqkv.scale[1] = 1.0f;
    gqkv.X[2] = xv; gqkv.W[2] = wv; gqkv.bias[2] = bv; gqkv.Y[2] = vv;
    gqkv.layout[2] = 1; gqkv.scale[2] = 1.0f;
    gemm_h<<<dim3(EMB / 128, ROWS / 128, 3), 256, GEMM_SMEM>>>(gqkv);

    attn_h<<<dim3(SEQ / 128, BH), 256, ATTN_SMEM>>>(qq, kk, vv, badj, at);

    GemmBatch go;
    go.X[0] = at; go.W[0] = wo; go.bias[0] = bo; go.Y[0] = d_out;
    go.layout[0] = 0; go.scale[0] = 1.0f;
    go.X[1] = at; go.W[1] = wo; go.bias[1] = bo; go.Y[1] = d_out;
    go.layout[1] = 0; go.scale[1] = 1.0f;
    go.X[2] = at; go.W[2] = wo; go.bias[2] = bo; go.Y[2] = d_out;
    go.layout[2] = 0; go.scale[2] = 1.0f;
    gemm_h<<<dim3(EMB / 128, ROWS / 128, 1), 256, GEMM_SMEM>>>(go);
}

// round 13
// speedup vs baseline: 1.2285x; 1.0123x over previous
#include <cuda_runtime.h>
#include <cuda_fp16.h>
#include <cstdint>

#define BATCH 2
#define SEQ   2048
#define EMB   1024
#define HEADS 16
#define HDIM  64
#define BH    (BATCH*HEADS)
#define ROWS  (BATCH*SEQ)

#define LOG2E 1.44269504f
#define MASK_NEG (-60000.0f)

// ---------------- scratch ----------------------------------------------------
__device__ __half g_xq[ROWS * EMB];
__device__ __half g_xk[ROWS * EMB];
__device__ __half g_xv[ROWS * EMB];
__device__ __half g_wq[EMB * EMB];
__device__ __half g_wk[EMB * EMB];
__device__ __half g_wv[EMB * EMB];
__device__ __half g_wo[EMB * EMB];
__device__ __half g_q[BH * SEQ * HDIM];    // [bh][s][d], pre-scaled log2e/8
__device__ __half g_k[BH * SEQ * HDIM];    // [bh][s][d]
__device__ __half g_v[BH * HDIM * SEQ];    // [bh][d][s]
__device__ __half g_attn[ROWS * EMB];      // [b*S+s][h*64+d]
__device__ __half g_badj[BATCH * SEQ * SEQ];  // (mask?adj*log2e:-60000), tile-permuted

// ---------------- helpers ---------------------------------------------------
__device__ __forceinline__ uint32_t pack_h2(float lo, float hi) {
    uint32_t r;
    asm("cvt.rn.f16x2.f32 %0, %1, %2;" : "=r"(r) : "f"(hi), "f"(lo));
    return r;
}
__device__ __forceinline__ float ex2(float x) {
    float y;
    asm("ex2.approx.ftz.f32 %0, %1;" : "=f"(y) : "f"(x));
    return y;
}
__device__ __forceinline__ uint32_t ex2_h2(uint32_t x) {
    uint32_t y;
    asm("ex2.approx.f16x2 %0, %1;" : "=r"(y) : "r"(x));
    return y;
}
__device__ __forceinline__ void mmaH(float* d, const uint32_t* a, uint32_t b0, uint32_t b1) {
    asm volatile(
        "mma.sync.aligned.m16n8k16.row.col.f32.f16.f16.f32 "
        "{%0,%1,%2,%3}, {%4,%5,%6,%7}, {%8,%9}, {%0,%1,%2,%3};"
        : "+f"(d[0]), "+f"(d[1]), "+f"(d[2]), "+f"(d[3])
        : "r"(a[0]), "r"(a[1]), "r"(a[2]), "r"(a[3]), "r"(b0), "r"(b1));
}
__device__ __forceinline__ void ldsm4(uint32_t* r, uint32_t addr) {
    asm volatile("ldmatrix.sync.aligned.m8n8.x4.shared.b16 {%0,%1,%2,%3}, [%4];"
                 : "=r"(r[0]), "=r"(r[1]), "=r"(r[2]), "=r"(r[3]) : "r"(addr));
}
__device__ __forceinline__ void cpa16(uint32_t dst, const void* src) {
    asm volatile("cp.async.cg.shared.global [%0], [%1], 16;" :: "r"(dst), "l"(src));
}
__device__ __forceinline__ void cp_commit() { asm volatile("cp.async.commit_group;"); }
template<int N> __device__ __forceinline__ void cp_wait() {
    asm volatile("cp.async.wait_group %0;" :: "n"(N));
}

// ---------------- pre-pass ---------------------------------------------------
struct CvtBatch { const float4* s[7]; __half2* d[7]; int n4[7]; };
__global__ void cvt_batch_k(CvtBatch a) {
    const float4* s = a.s[blockIdx.y];
    __half2* d = a.d[blockIdx.y];
    int n = a.n4[blockIdx.y];
    for (int i = blockIdx.x * 256 + threadIdx.x; i < n; i += gridDim.x * 256) {
        float4 v = s[i];
        d[2 * i]     = __floats2half2_rn(v.x, v.y);
        d[2 * i + 1] = __floats2half2_rn(v.z, v.w);
    }
}

// badj half2 writer (log2e-scaled): pair index p2 = j*8 + nt  <->  k = nt*8 + 2j
__global__ void make_badj_k(const float* __restrict__ adj, const int* __restrict__ mask,
                            __half2* __restrict__ out) {
    int idx = blockIdx.x * 256 + threadIdx.x;      // [0, B*S*S/2)
    int p2 = idx & 31;
    int base = idx >> 5;                           // (b*S+q)*32 + kt
    int kt = base & 31;
    int q  = (base >> 5) & 2047;
    int b  = base >> 16;
    int jj = p2 >> 3, nt = p2 & 7;
    int k = kt * 64 + nt * 8 + 2 * jj;
    float2 v = *reinterpret_cast<const float2*>(&adj[(size_t)q * SEQ + k]);
    int2 m = *reinterpret_cast<const int2*>(&mask[((size_t)b * SEQ + q) * SEQ + k]);
    out[idx] = __floats2half2_rn(m.x ? v.x * LOG2E : MASK_NEG,
                                 m.y ? v.y * LOG2E : MASK_NEG);
}

// ---------------- fp16 GEMM (unchanged) --------------------------------------
#define GEMM_SMEM 65536

struct GemmBatch {
    const __half* X[3]; const __half* W[3]; const float* bias[3];
    void* Y[3]; int layout[3]; float scale[3];
};

__global__ __launch_bounds__(256, 2) void gemm_h(GemmBatch args)
{
    extern __shared__ __align__(1024) char smem[];
    const uint32_t sb = (uint32_t)__cvta_generic_to_shared(smem);
    const int z = blockIdx.z;
    const __half* __restrict__ X = args.X[z];
    const __half* __restrict__ W = args.W[z];
    const float* __restrict__ bias = args.bias[z];
    void* Y = args.Y[z];
    const int layout = args.layout[z];
    const float scale = args.scale[z];

    const int tid = threadIdx.x, lane = tid & 31, wid = tid >> 5;
    const int g = lane >> 2, j = lane & 3;
    const int wm = (wid & 1) * 64, wn = (wid >> 1) * 32;
    const int m0 = blockIdx.y * 128, n0 = blockIdx.x * 128;

    const int c_ = tid & 7, r_ = tid >> 3;
    const uint32_t swz = (uint32_t)((c_ ^ (r_ & 7)) << 4);

    auto load_stage = [&](int c) {
        const uint32_t ab = sb + (uint32_t)(c & 1) * 16384u;
        const uint32_t bb = sb + 32768u + (uint32_t)(c & 1) * 16384u;
        const int k0 = c * 64;
#pragma unroll
        for (int i = 0; i < 4; ++i) {
            int row = r_ + i * 32;
            cpa16(ab + (uint32_t)row * 128u + swz,
                  X + (size_t)(m0 + row) * EMB + k0 + c_ * 8);
            cpa16(bb + (uint32_t)row * 128u + swz,
                  W + (size_t)(n0 + row) * EMB + k0 + c_ * 8);
        }
    };

    float acc[4][4][4];
#pragma unroll
    for (int mt = 0; mt < 4; ++mt)
#pragma unroll
        for (int nt = 0; nt < 4; ++nt)
#pragma unroll
            for (int c = 0; c < 4; ++c) acc[mt][nt][c] = 0.f;

    const int sr  = (lane & 7) + (((lane >> 3) & 1) << 3);
    const int e   = lane >> 4;
    const int sbr = (lane & 7) + ((lane >> 4) << 3);
    const int eb  = (lane >> 3) & 1;

    load_stage(0); cp_commit();
    for (int kt = 0; kt < 16; ++kt) {
        const int buf = kt & 1;
        if (kt + 1 < 16) load_stage(kt + 1);
        cp_commit();
        cp_wait<1>();
        __syncthreads();
        const uint32_t ab = sb + (uint32_t)buf * 16384u;
        const uint32_t bb = sb + 32768u + (uint32_t)buf * 16384u;
#pragma unroll
        for (int ks = 0; ks < 4; ++ks) {
            uint32_t afr[4][4];
#pragma unroll
            for (int mt = 0; mt < 4; ++mt) {
                int row = wm + mt * 16 + sr;
                ldsm4(afr[mt], ab + (uint32_t)row * 128u +
                               ((uint32_t)((ks * 2 + e) ^ (row & 7)) << 4));
            }
#pragma unroll
            for (int ntp = 0; ntp < 2; ++ntp) {
                int row = wn + ntp * 16 + sbr;
                uint32_t bfr[4];
                ldsm4(bfr, bb + (uint32_t)row * 128u +
                           ((uint32_t)((ks * 2 + eb) ^ (row & 7)) << 4));
#pragma unroll
                for (int mt = 0; mt < 4; ++mt) {
                    mmaH(acc[mt][2 * ntp],     afr[mt], bfr[0], bfr[1]);
                    mmaH(acc[mt][2 * ntp + 1], afr[mt], bfr[2], bfr[3]);
                }
            }
        }
        __syncthreads();
    }

#pragma unroll
    for (int nt = 0; nt < 4; ++nt) {
        int n = n0 + wn + nt * 8 + 2 * j;
        float2 bb2 = *reinterpret_cast<const float2*>(&bias[n]);
#pragma unroll
        for (int mt = 0; mt < 4; ++mt) {
            int m = m0 + wm + mt * 16 + g;
            float v00 = (acc[mt][nt][0] + bb2.x) * scale;
            float v01 = (acc[mt][nt][1] + bb2.y) * scale;
            float v10 = (acc[mt][nt][2] + bb2.x) * scale;
            float v11 = (acc[mt][nt][3] + bb2.y) * scale;
            if (layout == 0) {
                float* Yf = (float*)Y;
                *reinterpret_cast<float2*>(&Yf[(size_t)m * EMB + n]) = make_float2(v00, v01);
                *reinterpret_cast<float2*>(&Yf[(size_t)(m + 8) * EMB + n]) = make_float2(v10, v11);
            } else {
                __half* Yh = (__half*)Y;
                int bI = m >> 11, s = m & 2047, h = n >> 6, d = n & 63;
                if (layout == 2) {
                    size_t base = ((size_t)(bI * HEADS + h) * SEQ + s) * HDIM + d;
                    *reinterpret_cast<__half2*>(&Yh[base]) = __floats2half2_rn(v00, v01);
                    *reinterpret_cast<__half2*>(&Yh[base + 8 * HDIM]) = __floats2half2_rn(v10, v11);
                } else {
                    size_t base = ((size_t)(bI * HEADS + h) * HDIM + d) * SEQ + s;
                    Yh[base]           = __float2half_rn(v00);
                    Yh[base + SEQ]     = __float2half_rn(v01);
                    Yh[base + 8]       = __float2half_rn(v10);
                    Yh[base + SEQ + 8] = __float2half_rn(v11);
                }
            }
        }
    }
}

// ---------------- flash attention: f16x2 exp, ones-mma row sums --------------
#define QS_B   0u
#define STG_B  16384u
#define STG_SZ 16384u
#define ATTN_SMEM 65536
#define ONE2 0x3C003C00u   // half2(1.0, 1.0)

__global__ __launch_bounds__(256, 2) void attn_h(
    const __half* __restrict__ Qg, const __half* __restrict__ Kg,
    const __half* __restrict__ Vg, const __half* __restrict__ badj,
    __half* __restrict__ outp)
{
    extern __shared__ __align__(1024) char sm8[];
    const uint32_t sb = (uint32_t)__cvta_generic_to_shared(sm8);
    const int tid = threadIdx.x, lane = tid & 31, w = tid >> 5;
    const int g = lane >> 2, j = lane & 3;
    const int bh = blockIdx.y, b = bh >> 4, h = bh & 15;
    const int q0 = blockIdx.x * 128;

    const int c_ = tid & 7, r_ = tid >> 3;
    const uint32_t swz = (uint32_t)((c_ ^ (r_ & 7)) << 4);

    auto load_kv = [&](int t) {
        const uint32_t stb = sb + STG_B + (uint32_t)(t % 3) * STG_SZ;
        const int kn = t * 64;
#pragma unroll
        for (int i = 0; i < 2; ++i) {
            int row = r_ + i * 32;
            cpa16(stb + (uint32_t)row * 128u + swz,
                  Kg + ((size_t)bh * SEQ + kn + row) * HDIM + c_ * 8);
            cpa16(stb + 8192u + (uint32_t)row * 128u + swz,
                  Vg + ((size_t)bh * HDIM + row) * SEQ + kn + c_ * 8);
        }
    };

#pragma unroll
    for (int i = 0; i < 4; ++i) {
        int row = r_ + i * 32;
        cpa16(sb + QS_B + (uint32_t)row * 128u + swz,
              Qg + ((size_t)bh * SEQ + q0 + row) * HDIM + c_ * 8);
    }
    load_kv(0); cp_commit();
    load_kv(1); cp_commit();

    float o[8][4];
    float lacc[4] = {0.f, 0.f, 0.f, 0.f};     // P-rowsum mma accumulator
    float mrun[2] = {-1e30f, -1e30f};
#pragma unroll
    for (int nt = 0; nt < 8; ++nt)
#pragma unroll
        for (int c = 0; c < 4; ++c) o[nt][c] = 0.f;

    const int sr  = (lane & 7) + (((lane >> 3) & 1) << 3);
    const int e   = lane >> 4;
    const int sbr = (lane & 7) + ((lane >> 4) << 3);
    const int eb  = (lane >> 3) & 1;
    const int arow = w * 16 + sr;
    const uint32_t qab = sb + QS_B + (uint32_t)arow * 128u;

    const __half* bj0 = badj + (((size_t)b * SEQ + (q0 + w * 16 + g)) << 11) + (j << 4);
    const __half* bj1 = badj + (((size_t)b * SEQ + (q0 + w * 16 + g + 8)) << 11) + (j << 4);

    uint32_t qf[4][4];

    for (int kt = 0; kt < 32; ++kt) {
        const uint32_t stb = sb + STG_B + (uint32_t)(kt % 3) * STG_SZ;

        // badj prefetch before barrier: L2 latency hides under it
        uint32_t pb[2][8];
#pragma unroll
        for (int r = 0; r < 2; ++r) {
            const __half* bp = (r ? bj1 : bj0) + (kt << 6);
            uint4 u0 = *reinterpret_cast<const uint4*>(bp);
            uint4 u1 = *reinterpret_cast<const uint4*>(bp + 8);
            pb[r][0] = u0.x; pb[r][1] = u0.y; pb[r][2] = u0.z; pb[r][3] = u0.w;
            pb[r][4] = u1.x; pb[r][5] = u1.y; pb[r][6] = u1.z; pb[r][7] = u1.w;
        }

        cp_wait<1>();
        __syncthreads();

        if (kt + 2 < 32) load_kv(kt + 2);
        cp_commit();

        if (kt == 0) {
#pragma unroll
            for (int ks = 0; ks < 4; ++ks)
                ldsm4(qf[ks], qab + ((uint32_t)((ks * 2 + e) ^ (arow & 7)) << 4));
        }

        // ---- sacc initialized with badj (mma C-operand bias) ----
        float sacc[8][4];
#pragma unroll
        for (int r = 0; r < 2; ++r)
#pragma unroll
            for (int nt = 0; nt < 8; ++nt) {
                float2 ad = __half22float2(*reinterpret_cast<__half2*>(&pb[r][nt]));
                sacc[nt][r * 2]     = ad.x;
                sacc[nt][r * 2 + 1] = ad.y;
            }

        // ---- S = badj + Q K^T (log2 domain) ----
#pragma unroll
        for (int ks = 0; ks < 4; ++ks) {
#pragma unroll
            for (int ntp = 0; ntp < 4; ++ntp) {
                int row = ntp * 16 + sbr;
                uint32_t bf[4];
                ldsm4(bf, stb + (uint32_t)row * 128u +
                          ((uint32_t)((ks * 2 + eb) ^ (row & 7)) << 4));
                mmaH(sacc[2 * ntp],     qf[ks], bf[0], bf[1]);
                mmaH(sacc[2 * ntp + 1], qf[ks], bf[2], bf[3]);
            }
        }

        // ---- online softmax: f16x2 exp2 straight into P fragments ----
        uint32_t pf[4][4];
#pragma unroll
        for (int r = 0; r < 2; ++r) {
            float rowm = sacc[0][r * 2];
#pragma unroll
            for (int nt = 0; nt < 8; ++nt)
                rowm = fmaxf(rowm, fmaxf(sacc[nt][r * 2], sacc[nt][r * 2 + 1]));
            rowm = fmaxf(rowm, __shfl_xor_sync(0xffffffffu, rowm, 1));
            rowm = fmaxf(rowm, __shfl_xor_sync(0xffffffffu, rowm, 2));
            const float mn = fmaxf(rowm, mrun[r]);
            if (mn > mrun[r]) {           // max improved: rescale o and lacc
                float al = ex2(mrun[r] - mn);
                mrun[r] = mn;
                lacc[2 * r] *= al; lacc[2 * r + 1] *= al;
#pragma unroll
                for (int nt = 0; nt < 8; ++nt) {
                    o[nt][2 * r] *= al; o[nt][2 * r + 1] *= al;
                }
            }
#pragma unroll
            for (int nt = 0; nt < 8; ++nt) {
                float d0 = sacc[nt][r * 2]     - mn;
                float d1 = sacc[nt][r * 2 + 1] - mn;
                pf[nt >> 1][((nt & 1) << 1) | r] = ex2_h2(pack_h2(d0, d1));
            }
        }

        // ---- O += P V; l += P 1 (ones-mma row sum, exact fp32) ----
        const uint32_t vb = stb + 8192u;
#pragma unroll
        for (int t = 0; t < 4; ++t) {
            mmaH(lacc, pf[t], ONE2, ONE2);
#pragma unroll
            for (int ntp = 0; ntp < 4; ++ntp) {
                int row = ntp * 16 + sbr;
                uint32_t bf[4];
                ldsm4(bf, vb + (uint32_t)row * 128u +
                          ((uint32_t)((t * 2 + eb) ^ (row & 7)) << 4));
                mmaH(o[2 * ntp],     pf[t], bf[0], bf[1]);
                mmaH(o[2 * ntp + 1], pf[t], bf[2], bf[3]);
            }
        }
    }

    // epilogue: lacc holds exact row sums (already reduced by mma)
    const float inv0 = 1.f / lacc[0], inv1 = 1.f / lacc[2];
    const int qa = q0 + w * 16 + g;
#pragma unroll
    for (int nt = 0; nt < 8; ++nt) {
        int dcol = h * HDIM + nt * 8 + 2 * j;
        *reinterpret_cast<__half2*>(&outp[((size_t)b * SEQ + qa) * EMB + dcol]) =
            __floats2half2_rn(o[nt][0] * inv0, o[nt][1] * inv0);
        *reinterpret_cast<__half2*>(&outp[((size_t)b * SEQ + qa + 8) * EMB + dcol]) =
            __floats2half2_rn(o[nt][2] * inv1, o[nt][3] * inv1);
    }
}

// ---------------- launch -----------------------------------------------------
extern "C" void kernel_launch(void* const* d_in, const int* in_sizes, int n_in,
                              void* d_out, int out_size)
{
    const float* query = (const float*)d_in[0];
    const float* key   = (const float*)d_in[1];
    const float* value = (const float*)d_in[2];
    const float* adj   = (const float*)d_in[3];
    const int*   mask  = (const int*)d_in[4];
    const float* Wq = (const float*)d_in[5];
    const float* bq = (const float*)d_in[6];
    const float* Wk = (const float*)d_in[7];
    const float* bk = (const float*)d_in[8];
    const float* Wv = (const float*)d_in[9];
    const float* bv = (const float*)d_in[10];
    const float* Wo = (const float*)d_in[11];
    const float* bo = (const float*)d_in[12];

    __half *xq, *xk, *xv, *wq, *wk, *wv, *wo, *qq, *kk, *vv, *at, *badj;
    cudaGetSymbolAddress((void**)&xq, g_xq);
    cudaGetSymbolAddress((void**)&xk, g_xk);
    cudaGetSymbolAddress((void**)&xv, g_xv);
    cudaGetSymbolAddress((void**)&wq, g_wq);
    cudaGetSymbolAddress((void**)&wk, g_wk);
    cudaGetSymbolAddress((void**)&wv, g_wv);
    cudaGetSymbolAddress((void**)&wo, g_wo);
    cudaGetSymbolAddress((void**)&qq, g_q);
    cudaGetSymbolAddress((void**)&kk, g_k);
    cudaGetSymbolAddress((void**)&vv, g_v);
    cudaGetSymbolAddress((void**)&at, g_attn);
    cudaGetSymbolAddress((void**)&badj, g_badj);

    cudaFuncSetAttribute(attn_h, cudaFuncAttributeMaxDynamicSharedMemorySize, ATTN_SMEM);
    cudaFuncSetAttribute(gemm_h, cudaFuncAttributeMaxDynamicSharedMemorySize, GEMM_SMEM);

    CvtBatch cb;
    cb.s[0] = (const float4*)query; cb.d[0] = (__half2*)xq; cb.n4[0] = ROWS * EMB / 4;
    cb.s[1] = (const float4*)key;   cb.d[1] = (__half2*)xk; cb.n4[1] = ROWS * EMB / 4;
    cb.s[2] = (const float4*)value; cb.d[2] = (__half2*)xv; cb.n4[2] = ROWS * EMB / 4;
    cb.s[3] = (const float4*)Wq;    cb.d[3] = (__half2*)wq; cb.n4[3] = EMB * EMB / 4;
    cb.s[4] = (const float4*)Wk;    cb.d[4] = (__half2*)wk; cb.n4[4] = EMB * EMB / 4;
    cb.s[5] = (const float4*)Wv;    cb.d[5] = (__half2*)wv; cb.n4[5] = EMB * EMB / 4;
    cb.s[6] = (const float4*)Wo;    cb.d[6] = (__half2*)wo; cb.n4[6] = EMB * EMB / 4;
    cvt_batch_k<<<dim3(1024, 7), 256>>>(cb);
    make_badj_k<<<(BATCH * SEQ * SEQ / 2) / 256, 256>>>(adj, mask, (__half2*)badj);

    GemmBatch gqkv;
    gqkv.X[0] = xq; gqkv.W[0] = wq; gqkv.bias[0] = bq; gqkv.Y[0] = qq;
    gqkv.layout[0] = 2; gqkv.scale[0] = 0.125f * LOG2E;
    gqkv.X[1] = xk; gqkv.W[1] = wk; gqkv.bias[1] = bk; gqkv.Y[1] = kk;
    gqkv.layout[1] = 2; gqkv.scale[1] = 1.0f;
    gqkv.X[2] = xv; gqkv.W[2] = wv; gqkv.bias[2] = bv; gqkv.Y[2] = vv;
    gqkv.layout[2] = 1; gqkv.scale[2] = 1.0f;
    gemm_h<<<dim3(EMB / 128, ROWS / 128, 3), 256, GEMM_SMEM>>>(gqkv);

    attn_h<<<dim3(SEQ / 128, BH), 256, ATTN_SMEM>>>(qq, kk, vv, badj, at);

    GemmBatch go;
    go.X[0] = at; go.W[0] = wo; go.bias[0] = bo; go.Y[0] = d_out;
    go.layout[0] = 0; go.scale[0] = 1.0f;
    go.X[1] = at; go.W[1] = wo; go.bias[1] = bo; go.Y[1] = d_out;
    go.layout[1] = 0; go.scale[1] = 1.0f;
    go.X[2] = at; go.W[2] = wo; go.bias[2] = bo; go.Y[2] = d_out;
    go.layout[2] = 0; go.scale[2] = 1.0f;
    gemm_h<<<dim3(EMB / 128, ROWS / 128, 1), 256, GEMM_SMEM>>>(go);
}

// round 14
// speedup vs baseline: 1.2744x; 1.0374x over previous
#include <cuda_runtime.h>
#include <cuda_fp16.h>
#include <cstdint>

#define BATCH 2
#define SEQ   2048
#define EMB   1024
#define HEADS 16
#define HDIM  64
#define BH    (BATCH*HEADS)
#define ROWS  (BATCH*SEQ)

#define LOG2E 1.44269504f
#define MASK_NEG (-60000.0f)

// ---------------- scratch ----------------------------------------------------
__device__ __half g_xq[ROWS * EMB];
__device__ __half g_xk[ROWS * EMB];
__device__ __half g_xv[ROWS * EMB];
__device__ __half g_wq[EMB * EMB];
__device__ __half g_wk[EMB * EMB];
__device__ __half g_wv[EMB * EMB];
__device__ __half g_wo[EMB * EMB];
__device__ __half g_q[BH * SEQ * HDIM];    // [bh][s][d], pre-scaled log2e/8
__device__ __half g_k[BH * SEQ * HDIM];    // [bh][s][d]
__device__ __half g_v[BH * HDIM * SEQ];    // [bh][d][s]
__device__ __half g_attn[ROWS * EMB];      // [b*S+s][h*64+d]
__device__ __half g_badj[BATCH * SEQ * SEQ];  // (mask?adj*log2e:-60000), tile-permuted

// ---------------- helpers ---------------------------------------------------
__device__ __forceinline__ uint32_t pack_h2(float lo, float hi) {
    uint32_t r;
    asm("cvt.rn.f16x2.f32 %0, %1, %2;" : "=r"(r) : "f"(hi), "f"(lo));
    return r;
}
__device__ __forceinline__ float ex2(float x) {
    float y;
    asm("ex2.approx.ftz.f32 %0, %1;" : "=f"(y) : "f"(x));
    return y;
}
__device__ __forceinline__ uint32_t ex2_h2(uint32_t x) {
    uint32_t y;
    asm("ex2.approx.f16x2 %0, %1;" : "=r"(y) : "r"(x));
    return y;
}
__device__ __forceinline__ void mmaH(float* d, const uint32_t* a, uint32_t b0, uint32_t b1) {
    asm volatile(
        "mma.sync.aligned.m16n8k16.row.col.f32.f16.f16.f32 "
        "{%0,%1,%2,%3}, {%4,%5,%6,%7}, {%8,%9}, {%0,%1,%2,%3};"
        : "+f"(d[0]), "+f"(d[1]), "+f"(d[2]), "+f"(d[3])
        : "r"(a[0]), "r"(a[1]), "r"(a[2]), "r"(a[3]), "r"(b0), "r"(b1));
}
__device__ __forceinline__ void ldsm4(uint32_t* r, uint32_t addr) {
    asm volatile("ldmatrix.sync.aligned.m8n8.x4.shared.b16 {%0,%1,%2,%3}, [%4];"
                 : "=r"(r[0]), "=r"(r[1]), "=r"(r[2]), "=r"(r[3]) : "r"(addr));
}
__device__ __forceinline__ void cpa16(uint32_t dst, const void* src) {
    asm volatile("cp.async.cg.shared.global [%0], [%1], 16;" :: "r"(dst), "l"(src));
}
__device__ __forceinline__ void cp_commit() { asm volatile("cp.async.commit_group;"); }
template<int N> __device__ __forceinline__ void cp_wait() {
    asm volatile("cp.async.wait_group %0;" :: "n"(N));
}

// ---------------- merged pre-pass (cvt x7 + badj) ----------------------------
struct CvtBatch { const float4* s[7]; __half2* d[7]; int n4[7]; };
__global__ void prepass_k(CvtBatch a, const float* __restrict__ adj,
                          const int* __restrict__ mask, __half2* __restrict__ bout) {
    if (blockIdx.y < 7) {
        const float4* s = a.s[blockIdx.y];
        __half2* d = a.d[blockIdx.y];
        int n = a.n4[blockIdx.y];
        for (int i = blockIdx.x * 256 + threadIdx.x; i < n; i += gridDim.x * 256) {
            float4 v = s[i];
            d[2 * i]     = __floats2half2_rn(v.x, v.y);
            d[2 * i + 1] = __floats2half2_rn(v.z, v.w);
        }
    } else {
        // badj: pair index p2 = j*8 + nt  <->  k = kt*64 + nt*8 + 2j
        const int total = BATCH * SEQ * SEQ / 2;
        for (int idx = blockIdx.x * 256 + threadIdx.x; idx < total;
             idx += gridDim.x * 256) {
            int p2 = idx & 31;
            int base = idx >> 5;
            int kt = base & 31;
            int q  = (base >> 5) & 2047;
            int b  = base >> 16;
            int jj = p2 >> 3, nt = p2 & 7;
            int k = kt * 64 + nt * 8 + 2 * jj;
            float2 v = *reinterpret_cast<const float2*>(&adj[(size_t)q * SEQ + k]);
            int2 m = *reinterpret_cast<const int2*>(&mask[((size_t)b * SEQ + q) * SEQ + k]);
            bout[idx] = __floats2half2_rn(m.x ? v.x * LOG2E : MASK_NEG,
                                          m.y ? v.y * LOG2E : MASK_NEG);
        }
    }
}

// ---------------- fp16 GEMM: single-barrier 2-stage pipeline -----------------
#define GEMM_SMEM 65536

struct GemmBatch {
    const __half* X[3]; const __half* W[3]; const float* bias[3];
    void* Y[3]; int layout[3]; float scale[3];
};

__global__ __launch_bounds__(256, 2) void gemm_h(GemmBatch args)
{
    extern __shared__ __align__(1024) char smem[];
    const uint32_t sb = (uint32_t)__cvta_generic_to_shared(smem);
    const int z = blockIdx.z;
    const __half* __restrict__ X = args.X[z];
    const __half* __restrict__ W = args.W[z];
    const float* __restrict__ bias = args.bias[z];
    void* Y = args.Y[z];
    const int layout = args.layout[z];
    const float scale = args.scale[z];

    const int tid = threadIdx.x, lane = tid & 31, wid = tid >> 5;
    const int g = lane >> 2, j = lane & 3;
    const int wm = (wid & 1) * 64, wn = (wid >> 1) * 32;
    const int m0 = blockIdx.y * 128, n0 = blockIdx.x * 128;

    const int c_ = tid & 7, r_ = tid >> 3;
    const uint32_t swz = (uint32_t)((c_ ^ (r_ & 7)) << 4);

    auto load_stage = [&](int c) {
        const uint32_t ab = sb + (uint32_t)(c & 1) * 16384u;
        const uint32_t bb = sb + 32768u + (uint32_t)(c & 1) * 16384u;
        const int k0 = c * 64;
#pragma unroll
        for (int i = 0; i < 4; ++i) {
            int row = r_ + i * 32;
            cpa16(ab + (uint32_t)row * 128u + swz,
                  X + (size_t)(m0 + row) * EMB + k0 + c_ * 8);
            cpa16(bb + (uint32_t)row * 128u + swz,
                  W + (size_t)(n0 + row) * EMB + k0 + c_ * 8);
        }
    };

    float acc[4][4][4];
#pragma unroll
    for (int mt = 0; mt < 4; ++mt)
#pragma unroll
        for (int nt = 0; nt < 4; ++nt)
#pragma unroll
            for (int c = 0; c < 4; ++c) acc[mt][nt][c] = 0.f;

    const int sr  = (lane & 7) + (((lane >> 3) & 1) << 3);
    const int e   = lane >> 4;
    const int sbr = (lane & 7) + ((lane >> 4) << 3);
    const int eb  = (lane >> 3) & 1;

    load_stage(0); cp_commit();
    for (int kt = 0; kt < 16; ++kt) {
        const int buf = kt & 1;
        cp_wait<0>();          // tile kt resident
        __syncthreads();       // all warps done with buf^1 (tile kt-1)
        if (kt + 1 < 16) load_stage(kt + 1);
        cp_commit();           // load kt+1 overlaps compute kt
        const uint32_t ab = sb + (uint32_t)buf * 16384u;
        const uint32_t bb = sb + 32768u + (uint32_t)buf * 16384u;
#pragma unroll
        for (int ks = 0; ks < 4; ++ks) {
            uint32_t afr[4][4];
#pragma unroll
            for (int mt = 0; mt < 4; ++mt) {
                int row = wm + mt * 16 + sr;
                ldsm4(afr[mt], ab + (uint32_t)row * 128u +
                               ((uint32_t)((ks * 2 + e) ^ (row & 7)) << 4));
            }
#pragma unroll
            for (int ntp = 0; ntp < 2; ++ntp) {
                int row = wn + ntp * 16 + sbr;
                uint32_t bfr[4];
                ldsm4(bfr, bb + (uint32_t)row * 128u +
                           ((uint32_t)((ks * 2 + eb) ^ (row & 7)) << 4));
#pragma unroll
                for (int mt = 0; mt < 4; ++mt) {
                    mmaH(acc[mt][2 * ntp],     afr[mt], bfr[0], bfr[1]);
                    mmaH(acc[mt][2 * ntp + 1], afr[mt], bfr[2], bfr[3]);
                }
            }
        }
    }

#pragma unroll
    for (int nt = 0; nt < 4; ++nt) {
        int n = n0 + wn + nt * 8 + 2 * j;
        float2 bb2 = *reinterpret_cast<const float2*>(&bias[n]);
#pragma unroll
        for (int mt = 0; mt < 4; ++mt) {
            int m = m0 + wm + mt * 16 + g;
            float v00 = (acc[mt][nt][0] + bb2.x) * scale;
            float v01 = (acc[mt][nt][1] + bb2.y) * scale;
            float v10 = (acc[mt][nt][2] + bb2.x) * scale;
            float v11 = (acc[mt][nt][3] + bb2.y) * scale;
            if (layout == 0) {
                float* Yf = (float*)Y;
                *reinterpret_cast<float2*>(&Yf[(size_t)m * EMB + n]) = make_float2(v00, v01);
                *reinterpret_cast<float2*>(&Yf[(size_t)(m + 8) * EMB + n]) = make_float2(v10, v11);
            } else {
                __half* Yh = (__half*)Y;
                int bI = m >> 11, s = m & 2047, h = n >> 6, d = n & 63;
                if (layout == 2) {
                    size_t base = ((size_t)(bI * HEADS + h) * SEQ + s) * HDIM + d;
                    *reinterpret_cast<__half2*>(&Yh[base]) = __floats2half2_rn(v00, v01);
                    *reinterpret_cast<__half2*>(&Yh[base + 8 * HDIM]) = __floats2half2_rn(v10, v11);
                } else {
                    size_t base = ((size_t)(bI * HEADS + h) * HDIM + d) * SEQ + s;
                    Yh[base]           = __float2half_rn(v00);
                    Yh[base + SEQ]     = __float2half_rn(v01);
                    Yh[base + 8]       = __float2half_rn(v10);
                    Yh[base + SEQ + 8] = __float2half_rn(v11);
                }
            }
        }
    }
}

// ---------------- flash attention: interleaved softmax reductions ------------
#define QS_B   0u
#define STG_B  16384u
#define STG_SZ 16384u
#define ATTN_SMEM 65536
#define ONE2 0x3C003C00u   // half2(1.0, 1.0)

__global__ __launch_bounds__(256, 2) void attn_h(
    const __half* __restrict__ Qg, const __half* __restrict__ Kg,
    const __half* __restrict__ Vg, const __half* __restrict__ badj,
    __half* __restrict__ outp)
{
    extern __shared__ __align__(1024) char sm8[];
    const uint32_t sb = (uint32_t)__cvta_generic_to_shared(sm8);
    const int tid = threadIdx.x, lane = tid & 31, w = tid >> 5;
    const int g = lane >> 2, j = lane & 3;
    const int bh = blockIdx.y, b = bh >> 4, h = bh & 15;
    const int q0 = blockIdx.x * 128;

    const int c_ = tid & 7, r_ = tid >> 3;
    const uint32_t swz = (uint32_t)((c_ ^ (r_ & 7)) << 4);

    auto load_kv = [&](int t) {
        const uint32_t stb = sb + STG_B + (uint32_t)(t % 3) * STG_SZ;
        const int kn = t * 64;
#pragma unroll
        for (int i = 0; i < 2; ++i) {
            int row = r_ + i * 32;
            cpa16(stb + (uint32_t)row * 128u + swz,
                  Kg + ((size_t)bh * SEQ + kn + row) * HDIM + c_ * 8);
            cpa16(stb + 8192u + (uint32_t)row * 128u + swz,
                  Vg + ((size_t)bh * HDIM + row) * SEQ + kn + c_ * 8);
        }
    };

#pragma unroll
    for (int i = 0; i < 4; ++i) {
        int row = r_ + i * 32;
        cpa16(sb + QS_B + (uint32_t)row * 128u + swz,
              Qg + ((size_t)bh * SEQ + q0 + row) * HDIM + c_ * 8);
    }
    load_kv(0); cp_commit();
    load_kv(1); cp_commit();

    float o[8][4];
    float lacc[4] = {0.f, 0.f, 0.f, 0.f};
    float mrun0 = -1e30f, mrun1 = -1e30f;
#pragma unroll
    for (int nt = 0; nt < 8; ++nt)
#pragma unroll
        for (int c = 0; c < 4; ++c) o[nt][c] = 0.f;

    const int sr  = (lane & 7) + (((lane >> 3) & 1) << 3);
    const int e   = lane >> 4;
    const int sbr = (lane & 7) + ((lane >> 4) << 3);
    const int eb  = (lane >> 3) & 1;
    const int arow = w * 16 + sr;
    const uint32_t qab = sb + QS_B + (uint32_t)arow * 128u;

    const __half* bj0 = badj + (((size_t)b * SEQ + (q0 + w * 16 + g)) << 11) + (j << 4);
    const __half* bj1 = badj + (((size_t)b * SEQ + (q0 + w * 16 + g + 8)) << 11) + (j << 4);

    uint32_t qf[4][4];

    for (int kt = 0; kt < 32; ++kt) {
        const uint32_t stb = sb + STG_B + (uint32_t)(kt % 3) * STG_SZ;

        // badj prefetch before barrier: L2 latency hides under it
        uint32_t pb[2][8];
#pragma unroll
        for (int r = 0; r < 2; ++r) {
            const __half* bp = (r ? bj1 : bj0) + (kt << 6);
            uint4 u0 = *reinterpret_cast<const uint4*>(bp);
            uint4 u1 = *reinterpret_cast<const uint4*>(bp + 8);
            pb[r][0] = u0.x; pb[r][1] = u0.y; pb[r][2] = u0.z; pb[r][3] = u0.w;
            pb[r][4] = u1.x; pb[r][5] = u1.y; pb[r][6] = u1.z; pb[r][7] = u1.w;
        }

        cp_wait<1>();
        __syncthreads();

        if (kt + 2 < 32) load_kv(kt + 2);
        cp_commit();

        if (kt == 0) {
#pragma unroll
            for (int ks = 0; ks < 4; ++ks)
                ldsm4(qf[ks], qab + ((uint32_t)((ks * 2 + e) ^ (arow & 7)) << 4));
        }

        // ---- sacc initialized with badj (mma C-operand bias) ----
        float sacc[8][4];
#pragma unroll
        for (int r = 0; r < 2; ++r)
#pragma unroll
            for (int nt = 0; nt < 8; ++nt) {
                float2 ad = __half22float2(*reinterpret_cast<__half2*>(&pb[r][nt]));
                sacc[nt][r * 2]     = ad.x;
                sacc[nt][r * 2 + 1] = ad.y;
            }

        // ---- S = badj + Q K^T (log2 domain) ----
#pragma unroll
        for (int ks = 0; ks < 4; ++ks) {
#pragma unroll
            for (int ntp = 0; ntp < 4; ++ntp) {
                int row = ntp * 16 + sbr;
                uint32_t bf[4];
                ldsm4(bf, stb + (uint32_t)row * 128u +
                          ((uint32_t)((ks * 2 + eb) ^ (row & 7)) << 4));
                mmaH(sacc[2 * ntp],     qf[ks], bf[0], bf[1]);
                mmaH(sacc[2 * ntp + 1], qf[ks], bf[2], bf[3]);
            }
        }

        // ---- online softmax: both rows' reduction chains interleaved ----
        float rowm0 = sacc[0][0], rowm1 = sacc[0][2];
#pragma unroll
        for (int nt = 0; nt < 8; ++nt) {
            rowm0 = fmaxf(rowm0, fmaxf(sacc[nt][0], sacc[nt][1]));
            rowm1 = fmaxf(rowm1, fmaxf(sacc[nt][2], sacc[nt][3]));
        }
        rowm0 = fmaxf(rowm0, __shfl_xor_sync(0xffffffffu, rowm0, 1));
        rowm1 = fmaxf(rowm1, __shfl_xor_sync(0xffffffffu, rowm1, 1));
        rowm0 = fmaxf(rowm0, __shfl_xor_sync(0xffffffffu, rowm0, 2));
        rowm1 = fmaxf(rowm1, __shfl_xor_sync(0xffffffffu, rowm1, 2));
        const float mn0 = fmaxf(rowm0, mrun0);
        const float mn1 = fmaxf(rowm1, mrun1);
        if (mn0 > mrun0) {
            float al = ex2(mrun0 - mn0);
            mrun0 = mn0;
            lacc[0] *= al; lacc[1] *= al;
#pragma unroll
            for (int nt = 0; nt < 8; ++nt) { o[nt][0] *= al; o[nt][1] *= al; }
        }
        if (mn1 > mrun1) {
            float al = ex2(mrun1 - mn1);
            mrun1 = mn1;
            lacc[2] *= al; lacc[3] *= al;
#pragma unroll
            for (int nt = 0; nt < 8; ++nt) { o[nt][2] *= al; o[nt][3] *= al; }
        }

        uint32_t pf[4][4];
#pragma unroll
        for (int nt = 0; nt < 8; ++nt) {
            pf[nt >> 1][(nt & 1) << 1] =
                ex2_h2(pack_h2(sacc[nt][0] - mn0, sacc[nt][1] - mn0));
            pf[nt >> 1][((nt & 1) << 1) | 1] =
                ex2_h2(pack_h2(sacc[nt][2] - mn1, sacc[nt][3] - mn1));
        }

        // ---- O += P V; l += P 1 (ones-mma row sum) ----
        const uint32_t vb = stb + 8192u;
#pragma unroll
        for (int t = 0; t < 4; ++t) {
            mmaH(lacc, pf[t], ONE2, ONE2);
#pragma unroll
            for (int ntp = 0; ntp < 4; ++ntp) {
                int row = ntp * 16 + sbr;
                uint32_t bf[4];
                ldsm4(bf, vb + (uint32_t)row * 128u +
                          ((uint32_t)((t * 2 + eb) ^ (row & 7)) << 4));
                mmaH(o[2 * ntp],     pf[t], bf[0], bf[1]);
                mmaH(o[2 * ntp + 1], pf[t], bf[2], bf[3]);
            }
        }
    }

    // epilogue
    const float inv0 = 1.f / lacc[0], inv1 = 1.f / lacc[2];
    const int qa = q0 + w * 16 + g;
#pragma unroll
    for (int nt = 0; nt < 8; ++nt) {
        int dcol = h * HDIM + nt * 8 + 2 * j;
        *reinterpret_cast<__half2*>(&outp[((size_t)b * SEQ + qa) * EMB + dcol]) =
            __floats2half2_rn(o[nt][0] * inv0, o[nt][1] * inv0);
        *reinterpret_cast<__half2*>(&outp[((size_t)b * SEQ + qa + 8) * EMB + dcol]) =
            __floats2half2_rn(o[nt][2] * inv1, o[nt][3] * inv1);
    }
}

// ---------------- launch -----------------------------------------------------
extern "C" void kernel_launch(void* const* d_in, const int* in_sizes, int n_in,
                              void* d_out, int out_size)
{
    const float* query = (const float*)d_in[0];
    const float* key   = (const float*)d_in[1];
    const float* value = (const float*)d_in[2];
    const float* adj   = (const float*)d_in[3];
    const int*   mask  = (const int*)d_in[4];
    const float* Wq = (const float*)d_in[5];
    const float* bq = (const float*)d_in[6];
    const float* Wk = (const float*)d_in[7];
    const float* bk = (const float*)d_in[8];
    const float* Wv = (const float*)d_in[9];
    const float* bv = (const float*)d_in[10];
    const float* Wo = (const float*)d_in[11];
    const float* bo = (const float*)d_in[12];

    __half *xq, *xk, *xv, *wq, *wk, *wv, *wo, *qq, *kk, *vv, *at, *badj;
    cudaGetSymbolAddress((void**)&xq, g_xq);
    cudaGetSymbolAddress((void**)&xk, g_xk);
    cudaGetSymbolAddress((void**)&xv, g_xv);
    cudaGetSymbolAddress((void**)&wq, g_wq);
    cudaGetSymbolAddress((void**)&wk, g_wk);
    cudaGetSymbolAddress((void**)&wv, g_wv);
    cudaGetSymbolAddress((void**)&wo, g_wo);
    cudaGetSymbolAddress((void**)&qq, g_q);
    cudaGetSymbolAddress((void**)&kk, g_k);
    cudaGetSymbolAddress((void**)&vv, g_v);
    cudaGetSymbolAddress((void**)&at, g_attn);
    cudaGetSymbolAddress((void**)&badj, g_badj);

    cudaFuncSetAttribute(attn_h, cudaFuncAttributeMaxDynamicSharedMemorySize, ATTN_SMEM);
    cudaFuncSetAttribute(gemm_h, cudaFuncAttributeMaxDynamicSharedMemorySize, GEMM_SMEM);

    CvtBatch cb;
    cb.s[0] = (const float4*)query; cb.d[0] = (__half2*)xq; cb.n4[0] = ROWS * EMB / 4;
    cb.s[1] = (const float4*)key;   cb.d[1] = (__half2*)xk; cb.n4[1] = ROWS * EMB / 4;
    cb.s[2] = (const float4*)value; cb.d[2] = (__half2*)xv; cb.n4[2] = ROWS * EMB / 4;
    cb.s[3] = (const float4*)Wq;    cb.d[3] = (__half2*)wq; cb.n4[3] = EMB * EMB / 4;
    cb.s[4] = (const float4*)Wk;    cb.d[4] = (__half2*)wk; cb.n4[4] = EMB * EMB / 4;
    cb.s[5] = (const float4*)Wv;    cb.d[5] = (__half2*)wv; cb.n4[5] = EMB * EMB / 4;
    cb.s[6] = (const float4*)Wo;    cb.d[6] = (__half2*)wo; cb.n4[6] = EMB * EMB / 4;
    prepass_k<<<dim3(1024, 8), 256>>>(cb, adj, mask, (__half2*)badj);

    GemmBatch gqkv;
    gqkv.X[0] = xq; gqkv.W[0] = wq; gqkv.bias[0] = bq; gqkv.Y[0] = qq;
    gqkv.layout[0] = 2; gqkv.scale[0] = 0.125f * LOG2E;
    gqkv.X[1] = xk; gqkv.W[1] = wk; gqkv.bias[1] = bk; gqkv.Y[1] = kk;
    gqkv.layout[1] = 2; gqkv.scale[1] = 1.0f;
    gqkv.X[2] = xv; gqkv.W[2] = wv; gqkv.bias[2] = bv; gqkv.Y[2] = vv;
    gqkv.layout[2] = 1; gqkv.scale[2] = 1.0f;
    gemm_h<<<dim3(EMB / 128, ROWS / 128, 3), 256, GEMM_SMEM>>>(gqkv);

    attn_h<<<dim3(SEQ / 128, BH), 256, ATTN_SMEM>>>(qq, kk, vv, badj, at);

    GemmBatch go;
    go.X[0] = at; go.W[0] = wo; go.bias[0] = bo; go.Y[0] = d_out;
    go.layout[0] = 0; go.scale[0] = 1.0f;
    go.X[1] = at; go.W[1] = wo; go.bias[1] = bo; go.Y[1] = d_out;
    go.layout[1] = 0; go.scale[1] = 1.0f;
    go.X[2] = at; go.W[2] = wo; go.bias[2] = bo; go.Y[2] = d_out;
    go.layout[2] = 0; go.scale[2] = 1.0f;
    gemm_h<<<dim3(EMB / 128, ROWS / 128, 1), 256, GEMM_SMEM>>>(go);
}